// round 2
// baseline (speedup 1.0000x reference)
#include <cuda_runtime.h>
#include <math.h>

#define BATCH 64
#define TT    2048
#define HH    128
#define DIN   108
#define LL    37

#define NBLK 128
#define NTHR 128

#define ACC1_OFF 1
#define ACC3_OFF 65
#define ACT_OFF  129
#define PRED_OFF (129 + BATCH*HH)

// device scratch (static, no allocations)
__device__ __align__(16) float g_h1[2][TT][HH][BATCH];   // layer0 outputs
__device__ __align__(16) float g_h2buf[2][2][HH][BATCH]; // [buf][branch]
__device__ __align__(16) float g_hf[2][HH][BATCH];
__device__ unsigned g_bar_count = 0;
__device__ unsigned g_bar_gen   = 0;

__device__ __forceinline__ float sigf(float x) { return 1.0f / (1.0f + expf(-x)); }

__device__ __forceinline__ void grid_barrier(unsigned* gen) {
    __syncthreads();
    if (threadIdx.x == 0) {
        unsigned target = *gen + 1u;
        __threadfence();
        if (atomicAdd(&g_bar_count, 1u) == gridDim.x - 1u) {
            g_bar_count = 0u;
            __threadfence();
            *((volatile unsigned*)&g_bar_gen) = target;
        } else {
            while (*((volatile unsigned*)&g_bar_gen) != target) { }
        }
        __threadfence();
        *gen = target;
    }
    __syncthreads();
}

// smem layout (floats)
#define OFF_W   0      // 2048
#define OFF_B   2048   // 8
#define OFF_C   2056   // 128
#define OFF_G   2184   // 512
#define OFF_M   2696   // 64
#define OFF_INA 2760   // 8192
#define OFF_INB 10952  // 8192
#define SMEM_FLOATS 19144

__global__ void __launch_bounds__(NTHR, 1)
lstm_persistent_kernel(
    const float* __restrict__ xl, const float* __restrict__ xr, const float* __restrict__ xo,
    const int* __restrict__ yv, const int* __restrict__ isl, const int* __restrict__ isr,
    const int* __restrict__ dur,
    const float* __restrict__ Wih0_l, const float* __restrict__ Whh0_l,
    const float* __restrict__ bih0_l, const float* __restrict__ bhh0_l,
    const float* __restrict__ Wih1_l, const float* __restrict__ Whh1_l,
    const float* __restrict__ bih1_l, const float* __restrict__ bhh1_l,
    const float* __restrict__ Wih0_r, const float* __restrict__ Whh0_r,
    const float* __restrict__ bih0_r, const float* __restrict__ bhh0_r,
    const float* __restrict__ Wih1_r, const float* __restrict__ Whh1_r,
    const float* __restrict__ bih1_r, const float* __restrict__ bhh1_r,
    const float* __restrict__ wcl, const float* __restrict__ bcl,
    const float* __restrict__ wcr, const float* __restrict__ bcr,
    const float* __restrict__ Wout, const float* __restrict__ bout,
    float* __restrict__ out)
{
    extern __shared__ float sm[];
    float* Wsm = sm + OFF_W;
    float* bsm = sm + OFF_B;
    float* csm = sm + OFF_C;
    float* gsm = sm + OFF_G;
    float* msm = sm + OFF_M;
    float* inA = sm + OFF_INA;
    float* inB = sm + OFF_INB;

    const int tid    = threadIdx.x;
    const int blk    = blockIdx.x;
    const int branch = blk >> 6;
    const int u0     = (blk & 63) * 2;
    const int rp     = tid >> 5;         // gate 0..3 (i,f,g,o)
    const int b0     = (tid & 31) * 2;   // batch pair

    unsigned gen = *((volatile unsigned*)&g_bar_gen);

    const float* Wih0 = branch ? Wih0_r : Wih0_l;
    const float* Whh0 = branch ? Whh0_r : Whh0_l;
    const float* bih0 = branch ? bih0_r : bih0_l;
    const float* bhh0 = branch ? bhh0_r : bhh0_l;
    const float* Wih1 = branch ? Wih1_r : Wih1_l;
    const float* Whh1 = branch ? Whh1_r : Whh1_l;
    const float* bih1 = branch ? bih1_r : bih1_l;
    const float* bhh1 = branch ? bhh1_r : bhh1_l;
    const int*   ish  = branch ? isr : isl;
    const float* xh   = branch ? xr  : xl;

    // ---------- phase 0: layer-0 ----------
    if (tid < BATCH) msm[tid] = (ish[tid] != 0) ? 1.0f : 0.0f;
    for (int i = tid; i < 8 * 236; i += NTHR) {
        int lr = i / 236, k = i % 236;
        int row = (lr >> 1) * HH + u0 + (lr & 1);
        float v = (k < DIN) ? Wih0[row * DIN + k] : Whh0[row * HH + (k - DIN)];
        Wsm[k * 8 + lr] = v;
    }
    if (tid < 8) {
        int row = (tid >> 1) * HH + u0 + (tid & 1);
        bsm[tid] = bih0[row] + bhh0[row];
    }
    if (tid < 128) csm[tid] = 0.0f;
    __syncthreads();

    for (int t = 0; t < TT; ++t) {
        for (int i = tid; i < BATCH * DIN; i += NTHR) {
            int b = i / DIN, d = i % DIN;
            float v = (d < 99) ? xh[(b * TT + t) * 99 + d] * msm[b]
                               : xo[(b * TT + t) * 9 + (d - 99)];
            inA[d * 65 + b] = v;
        }
        if (t == 0) {
            for (int i = tid; i < HH * BATCH; i += NTHR) inB[i] = 0.0f;
        } else {
            const float4* src = (const float4*)&g_h1[branch][t - 1][0][0];
            float4* dst = (float4*)inB;
            for (int i = tid; i < HH * BATCH / 4; i += NTHR) dst[i] = __ldcg(src + i);
        }
        __syncthreads();

        float a00 = bsm[2 * rp], a01 = a00;
        float a10 = bsm[2 * rp + 1], a11 = a10;
        #pragma unroll 4
        for (int k = 0; k < DIN; ++k) {
            float2 w = *(const float2*)&Wsm[k * 8 + 2 * rp];
            float vx = inA[k * 65 + b0];
            float vy = inA[k * 65 + b0 + 1];
            a00 += w.x * vx; a01 += w.x * vy;
            a10 += w.y * vx; a11 += w.y * vy;
        }
        #pragma unroll 8
        for (int k = 0; k < HH; ++k) {
            float2 w = *(const float2*)&Wsm[(DIN + k) * 8 + 2 * rp];
            float2 v = *(const float2*)&inB[k * 64 + b0];
            a00 += w.x * v.x; a01 += w.x * v.y;
            a10 += w.y * v.x; a11 += w.y * v.y;
        }
        gsm[(2 * rp) * 64 + b0]     = a00; gsm[(2 * rp) * 64 + b0 + 1]     = a01;
        gsm[(2 * rp + 1) * 64 + b0] = a10; gsm[(2 * rp + 1) * 64 + b0 + 1] = a11;
        __syncthreads();

        {
            int uu = tid >> 6, b = tid & 63;
            float ip = gsm[(0 + uu) * 64 + b];
            float fp = gsm[(2 + uu) * 64 + b];
            float gp = gsm[(4 + uu) * 64 + b];
            float op = gsm[(6 + uu) * 64 + b];
            float c = csm[uu * 64 + b];
            c = sigf(fp) * c + sigf(ip) * tanhf(gp);
            float h = sigf(op) * tanhf(c);
            csm[uu * 64 + b] = c;
            g_h1[branch][t][u0 + uu][b] = h;
        }
        grid_barrier(&gen);
    }

    // ---------- phase 1: layer-1 ----------
    for (int i = tid; i < 8 * 256; i += NTHR) {
        int lr = i >> 8, k = i & 255;
        int row = (lr >> 1) * HH + u0 + (lr & 1);
        float v = (k < HH) ? Wih1[row * HH + k] : Whh1[row * HH + (k - HH)];
        Wsm[k * 8 + lr] = v;
    }
    if (tid < 8) {
        int row = (tid >> 1) * HH + u0 + (tid & 1);
        bsm[tid] = bih1[row] + bhh1[row];
    }
    if (tid < 128) csm[tid] = 0.0f;
    if (tid < BATCH) msm[tid] = (float)dur[tid];   // reuse msm for duration
    __syncthreads();

    for (int t = 0; t < TT; ++t) {
        {
            const float4* s1 = (const float4*)&g_h1[branch][t][0][0];
            float4* dA = (float4*)inA;
            for (int i = tid; i < HH * BATCH / 4; i += NTHR) dA[i] = __ldcg(s1 + i);
        }
        if (t == 0) {
            for (int i = tid; i < HH * BATCH; i += NTHR) inB[i] = 0.0f;
        } else {
            const float4* s2 = (const float4*)&g_h2buf[(t - 1) & 1][branch][0][0];
            float4* dB = (float4*)inB;
            for (int i = tid; i < HH * BATCH / 4; i += NTHR) dB[i] = __ldcg(s2 + i);
        }
        __syncthreads();

        float a00 = bsm[2 * rp], a01 = a00;
        float a10 = bsm[2 * rp + 1], a11 = a10;
        #pragma unroll 8
        for (int k = 0; k < HH; ++k) {
            float2 w = *(const float2*)&Wsm[k * 8 + 2 * rp];
            float2 v = *(const float2*)&inA[k * 64 + b0];
            a00 += w.x * v.x; a01 += w.x * v.y;
            a10 += w.y * v.x; a11 += w.y * v.y;
        }
        #pragma unroll 8
        for (int k = 0; k < HH; ++k) {
            float2 w = *(const float2*)&Wsm[(HH + k) * 8 + 2 * rp];
            float2 v = *(const float2*)&inB[k * 64 + b0];
            a00 += w.x * v.x; a01 += w.x * v.y;
            a10 += w.y * v.x; a11 += w.y * v.y;
        }
        gsm[(2 * rp) * 64 + b0]     = a00; gsm[(2 * rp) * 64 + b0 + 1]     = a01;
        gsm[(2 * rp + 1) * 64 + b0] = a10; gsm[(2 * rp + 1) * 64 + b0 + 1] = a11;
        __syncthreads();

        {
            int uu = tid >> 6, b = tid & 63;
            float ip = gsm[(0 + uu) * 64 + b];
            float fp = gsm[(2 + uu) * 64 + b];
            float gp = gsm[(4 + uu) * 64 + b];
            float op = gsm[(6 + uu) * 64 + b];
            float c = csm[uu * 64 + b];
            c = sigf(fp) * c + sigf(ip) * tanhf(gp);
            float h = sigf(op) * tanhf(c);
            csm[uu * 64 + b] = c;
            g_h2buf[t & 1][branch][u0 + uu][b] = h;
            if ((float)(t + 1) == msm[b]) g_hf[branch][u0 + uu][b] = h;
        }
        grid_barrier(&gen);
    }

    // ---------- epilogue: CTA 0 ----------
    if (blk != 0) return;

    __shared__ float lsum[NTHR];
    float myloss = 0.0f;

    if (tid < BATCH) {
        int b = tid;
        float hl[HH + 2], hr[HH + 2], y3[HH];
        hl[0] = 0.0f; hl[HH + 1] = 0.0f;
        hr[0] = 0.0f; hr[HH + 1] = 0.0f;
        for (int j = 0; j < HH; ++j) {
            hl[j + 1] = __ldcg(&g_hf[0][j][b]);
            hr[j + 1] = __ldcg(&g_hf[1][j][b]);
        }
        float wl0 = wcl[0], wl1 = wcl[1], wl2 = wcl[2], bl = bcl[0];
        float wr0 = wcr[0], wr1 = wcr[1], wr2 = wcr[2], br = bcr[0];
        for (int j = 0; j < HH; ++j) {
            float vl = wl0 * hl[j] + wl1 * hl[j + 1] + wl2 * hl[j + 2] + bl;
            float vr = wr0 * hr[j] + wr1 * hr[j + 1] + wr2 * hr[j + 2] + br;
            y3[j] = vl + vr;
            out[ACT_OFF + b * HH + j] = tanhf(y3[j]) * 0.1f;
        }
        // logits + softmax
        float logits[LL];
        float mx = -1e30f;
        for (int l = 0; l < LL; ++l) {
            float s = bout[l];
            for (int j = 0; j < HH; ++j) s += y3[j] * Wout[l * HH + j];
            logits[l] = s;
            mx = fmaxf(mx, s);
        }
        float den = 0.0f;
        for (int l = 0; l < LL; ++l) { logits[l] = expf(logits[l] - mx); den += logits[l]; }
        float inv = 1.0f / den;
        int yb = yv[b];
        float py = 0.0f;
        for (int l = 0; l < LL; ++l) {
            float p = logits[l] * inv;
            logits[l] = p;
            out[PRED_OFF + b * LL + l] = p;
            if (l == yb) py = p;
        }
        // BCE terms
        for (int l = 0; l < LL; ++l) {
            float p = logits[l];
            float lp = fmaxf(logf(p), -100.0f);
            float lq = fmaxf(logf(1.0f - p), -100.0f);
            myloss += (l == yb) ? lp : lq;
        }
        // top-k rank (jax top_k: descending, ties by lower index)
        int rank = 0;
        for (int l = 0; l < LL; ++l) {
            if (logits[l] > py) rank++;
            else if (logits[l] == py && l < yb) rank++;
        }
        out[ACC1_OFF + b] = (rank == 0) ? 1.0f : 0.0f;
        out[ACC3_OFF + b] = (rank < 3) ? 1.0f : 0.0f;
    }

    lsum[tid] = myloss;
    __syncthreads();
    if (tid == 0) {
        float s = 0.0f;
        for (int i = 0; i < BATCH; ++i) s += lsum[i];
        out[0] = -s / (float)(BATCH * LL);
    }
}

extern "C" void kernel_launch(void* const* d_in, const int* in_sizes, int n_in,
                              void* d_out, int out_size) {
    (void)in_sizes; (void)n_in; (void)out_size;
    static bool attr_set = false;
    if (!attr_set) {
        cudaFuncSetAttribute(lstm_persistent_kernel,
                             cudaFuncAttributeMaxDynamicSharedMemorySize,
                             SMEM_FLOATS * (int)sizeof(float));
        attr_set = true;
    }
    lstm_persistent_kernel<<<NBLK, NTHR, SMEM_FLOATS * (int)sizeof(float)>>>(
        (const float*)d_in[0], (const float*)d_in[1], (const float*)d_in[2],
        (const int*)d_in[3], (const int*)d_in[4], (const int*)d_in[5],
        (const int*)d_in[6],
        (const float*)d_in[7],  (const float*)d_in[8],  (const float*)d_in[9],  (const float*)d_in[10],
        (const float*)d_in[11], (const float*)d_in[12], (const float*)d_in[13], (const float*)d_in[14],
        (const float*)d_in[15], (const float*)d_in[16], (const float*)d_in[17], (const float*)d_in[18],
        (const float*)d_in[19], (const float*)d_in[20], (const float*)d_in[21], (const float*)d_in[22],
        (const float*)d_in[23], (const float*)d_in[24], (const float*)d_in[25], (const float*)d_in[26],
        (const float*)d_in[27], (const float*)d_in[28],
        (float*)d_out);
}

// round 5
// speedup vs baseline: 2.4955x; 2.4955x over previous
#include <cuda_runtime.h>
#include <math.h>

#define BATCH 64
#define TT    2048
#define HH    128
#define DIN   108
#define LL    37

#define ACC1_OFF 1
#define ACC3_OFF 65
#define ACT_OFF  129
#define PRED_OFF (129 + BATCH*HH)

// ---------------- device scratch (static; no runtime allocation) ----------------
__device__ __align__(16) float g_pre[2][TT][512][BATCH];     // precomputed x@Wih0^T + biases
__device__ __align__(16) float g_h0ring[2][2][HH][BATCH];    // [slot][branch][unit][b]
__device__ __align__(16) float g_h2ring[2][2][HH][BATCH];
__device__ __align__(16) float g_hf[2][HH][BATCH];
__device__ unsigned g_flags[2][64];                           // per-branch arrival flags

__device__ __forceinline__ float sigf(float x)    { return 1.0f / (1.0f + __expf(-x)); }
__device__ __forceinline__ float tanhfast(float x){ return 2.0f / (1.0f + __expf(-2.0f * x)) - 1.0f; }

// ==================================================================
// Kernel 1: precompute gate inputs  pre[br][t][row][b]
//           row = gate*128 + unit;  pre = W_ih0 @ xcat + (b_ih0 + b_hh0)
// ==================================================================
#define GX_XS 0
#define GX_WS (DIN*68)
#define GX_BS (GX_WS + 64*113)
#define GEMM_SMEM_FLOATS (GX_BS + 64)

__global__ void __launch_bounds__(128)
pre_gemm_kernel(const float* __restrict__ xl, const float* __restrict__ xr,
                const float* __restrict__ xo,
                const int* __restrict__ isl, const int* __restrict__ isr,
                const float* __restrict__ Wl, const float* __restrict__ bil, const float* __restrict__ bhl,
                const float* __restrict__ Wr, const float* __restrict__ bir, const float* __restrict__ bhr)
{
    extern __shared__ float sg[];
    float* xs  = sg + GX_XS;   // [k][68]
    float* Wsm = sg + GX_WS;   // [lr][113]
    float* bsm = sg + GX_BS;   // [64]

    const int rb  = blockIdx.x;   // row block 0..7
    const int t   = blockIdx.y;
    const int br  = blockIdx.z;
    const int tid = threadIdx.x;

    const float* xh  = br ? xr  : xl;
    const int*   ish = br ? isr : isl;
    const float* W   = br ? Wr  : Wl;
    const float* bi  = br ? bir : bil;
    const float* bh  = br ? bhr : bhl;

    for (int i = tid; i < BATCH * DIN; i += 128) {
        int b = i / DIN, k = i - b * DIN;
        float v;
        if (k < 99) v = xh[(b * TT + t) * 99 + k] * ((ish[b] != 0) ? 1.0f : 0.0f);
        else        v = xo[(b * TT + t) * 9 + (k - 99)];
        xs[k * 68 + b] = v;
    }
    for (int i = tid; i < 64 * DIN; i += 128) {
        int lr = i / DIN, k = i - lr * DIN;
        Wsm[lr * 113 + k] = W[(rb * 64 + lr) * DIN + k];
    }
    if (tid < 64) bsm[tid] = bi[rb * 64 + tid] + bh[rb * 64 + tid];
    __syncthreads();

    const int rg = tid >> 4;          // 8 rows each
    const int b4 = (tid & 15) * 4;    // 4 batches

    float4 acc[8];
    #pragma unroll
    for (int j = 0; j < 8; ++j) {
        float bb = bsm[rg * 8 + j];
        acc[j] = make_float4(bb, bb, bb, bb);
    }
    #pragma unroll 4
    for (int k = 0; k < DIN; ++k) {
        float4 xv = *(const float4*)&xs[k * 68 + b4];
        #pragma unroll
        for (int j = 0; j < 8; ++j) {
            float w = Wsm[(rg * 8 + j) * 113 + k];
            acc[j].x += w * xv.x; acc[j].y += w * xv.y;
            acc[j].z += w * xv.z; acc[j].w += w * xv.w;
        }
    }
    #pragma unroll
    for (int j = 0; j < 8; ++j) {
        int row = rb * 64 + rg * 8 + j;
        *(float4*)&g_pre[br][t][row][b4] = acc[j];
    }
}

// ==================================================================
// Kernel 2: persistent wavefront recurrence (L0 step n + L1 step n-1).
// 128 CTAs; per-branch distributed flag barrier; 2049 sync intervals.
// ==================================================================
#define R_W0  0
#define R_W1  (R_W0 + HH*8)
#define R_B1  (R_W1 + 2*HH*8)
#define R_STA (R_B1 + 8)
#define R_STB (R_STA + HH*BATCH)
#define R_G0  (R_STB + HH*BATCH)
#define R_G1  (R_G0 + 8*64)
#define REC_SMEM_FLOATS (R_G1 + 8*64)

__global__ void __launch_bounds__(128, 1)
lstm_recurrent_kernel(const float* __restrict__ Whh0_l, const float* __restrict__ Whh0_r,
                      const float* __restrict__ Wih1_l, const float* __restrict__ Whh1_l,
                      const float* __restrict__ bih1_l, const float* __restrict__ bhh1_l,
                      const float* __restrict__ Wih1_r, const float* __restrict__ Whh1_r,
                      const float* __restrict__ bih1_r, const float* __restrict__ bhh1_r,
                      const int* __restrict__ dur)
{
    extern __shared__ float sm[];
    float* Wsm0 = sm + R_W0;
    float* Wsm1 = sm + R_W1;
    float* bsm1 = sm + R_B1;
    float* stA  = sm + R_STA;
    float* stB  = sm + R_STB;
    float* gsm0 = sm + R_G0;
    float* gsm1 = sm + R_G1;

    const int tid = threadIdx.x;
    const int blk = blockIdx.x;
    const int br  = blk >> 6;
    const int g   = blk & 63;
    const int u0  = g * 2;
    const int rp  = tid >> 5;
    const int b0  = (tid & 31) * 2;

    const float* Whh0 = br ? Whh0_r : Whh0_l;
    const float* Wih1 = br ? Wih1_r : Wih1_l;
    const float* Whh1 = br ? Whh1_r : Whh1_l;
    const float* bi1  = br ? bih1_r : bih1_l;
    const float* bh1  = br ? bhh1_r : bhh1_l;

    for (int i = tid; i < 8 * HH; i += 128) {
        int lr = i >> 7, k = i & 127;
        int row = (lr >> 1) * HH + u0 + (lr & 1);
        Wsm0[k * 8 + lr] = Whh0[row * HH + k];
    }
    for (int i = tid; i < 8 * 2 * HH; i += 128) {
        int lr = i >> 8, k = i & 255;
        int row = (lr >> 1) * HH + u0 + (lr & 1);
        Wsm1[k * 8 + lr] = (k < HH) ? Wih1[row * HH + k] : Whh1[row * HH + (k - HH)];
    }
    if (tid < 8) {
        int row = (tid >> 1) * HH + u0 + (tid & 1);
        bsm1[tid] = bi1[row] + bh1[row];
    }

    const int uu = tid >> 6, b = tid & 63;
    float c0 = 0.0f, c1 = 0.0f;
    const int durb = dur[b];

    const unsigned base = g_flags[br][g];
    unsigned* myflag = &g_flags[br][g];
    const unsigned* pollflag = &g_flags[br][tid & 63];

    const float* preb = &g_pre[br][0][0][0];
    const int row0 = rp * HH + u0;
    float2 p0 = __ldcs((const float2*)&preb[(0 * 512 + row0) * BATCH + b0]);
    float2 p1 = __ldcs((const float2*)&preb[(0 * 512 + row0 + 1) * BATCH + b0]);
    __syncthreads();

    for (int n = 0; n <= TT; ++n) {
        // ---- stage h tiles ----
        if (n == 0) {
            for (int i = tid; i < HH * BATCH / 4; i += 128)
                ((float4*)stA)[i] = make_float4(0.f, 0.f, 0.f, 0.f);
        } else {
            const float4* s = (const float4*)&g_h0ring[(n - 1) & 1][br][0][0];
            for (int i = tid; i < HH * BATCH / 4; i += 128)
                ((float4*)stA)[i] = __ldcg(s + i);
        }
        if (n <= 1) {
            for (int i = tid; i < HH * BATCH / 4; i += 128)
                ((float4*)stB)[i] = make_float4(0.f, 0.f, 0.f, 0.f);
        } else {
            const float4* s = (const float4*)&g_h2ring[n & 1][br][0][0];
            for (int i = tid; i < HH * BATCH / 4; i += 128)
                ((float4*)stB)[i] = __ldcg(s + i);
        }
        __syncthreads();

        // ---- layer-0 gates (step n) ----
        if (n < TT) {
            float a00 = p0.x, a01 = p0.y, a10 = p1.x, a11 = p1.y;
            if (n + 1 < TT) {
                p0 = __ldcs((const float2*)&preb[((n + 1) * 512 + row0) * BATCH + b0]);
                p1 = __ldcs((const float2*)&preb[((n + 1) * 512 + row0 + 1) * BATCH + b0]);
            }
            #pragma unroll 8
            for (int k = 0; k < HH; ++k) {
                float2 w = *(const float2*)&Wsm0[k * 8 + 2 * rp];
                float2 v = *(const float2*)&stA[k * 64 + b0];
                a00 += w.x * v.x; a01 += w.x * v.y;
                a10 += w.y * v.x; a11 += w.y * v.y;
            }
            *(float2*)&gsm0[(2 * rp) * 64 + b0]     = make_float2(a00, a01);
            *(float2*)&gsm0[(2 * rp + 1) * 64 + b0] = make_float2(a10, a11);
        }
        // ---- layer-1 gates (step n-1) ----
        if (n >= 1) {
            float a00 = bsm1[2 * rp], a01 = a00;
            float a10 = bsm1[2 * rp + 1], a11 = a10;
            #pragma unroll 8
            for (int k = 0; k < HH; ++k) {
                float2 w = *(const float2*)&Wsm1[k * 8 + 2 * rp];
                float2 v = *(const float2*)&stA[k * 64 + b0];
                a00 += w.x * v.x; a01 += w.x * v.y;
                a10 += w.y * v.x; a11 += w.y * v.y;
            }
            #pragma unroll 8
            for (int k = 0; k < HH; ++k) {
                float2 w = *(const float2*)&Wsm1[(HH + k) * 8 + 2 * rp];
                float2 v = *(const float2*)&stB[k * 64 + b0];
                a00 += w.x * v.x; a01 += w.x * v.y;
                a10 += w.y * v.x; a11 += w.y * v.y;
            }
            *(float2*)&gsm1[(2 * rp) * 64 + b0]     = make_float2(a00, a01);
            *(float2*)&gsm1[(2 * rp + 1) * 64 + b0] = make_float2(a10, a11);
        }
        __syncthreads();

        // ---- state updates ----
        if (n < TT) {
            float ip = gsm0[(0 + uu) * 64 + b];
            float fp = gsm0[(2 + uu) * 64 + b];
            float gp = gsm0[(4 + uu) * 64 + b];
            float op = gsm0[(6 + uu) * 64 + b];
            c0 = sigf(fp) * c0 + sigf(ip) * tanhfast(gp);
            float h = sigf(op) * tanhfast(c0);
            g_h0ring[n & 1][br][u0 + uu][b] = h;
        }
        if (n >= 1) {
            float ip = gsm1[(0 + uu) * 64 + b];
            float fp = gsm1[(2 + uu) * 64 + b];
            float gp = gsm1[(4 + uu) * 64 + b];
            float op = gsm1[(6 + uu) * 64 + b];
            c1 = sigf(fp) * c1 + sigf(ip) * tanhfast(gp);
            float h = sigf(op) * tanhfast(c1);
            g_h2ring[(n - 1) & 1][br][u0 + uu][b] = h;
            if (n - 1 == durb - 1) g_hf[br][u0 + uu][b] = h;
        }

        // ---- per-branch distributed barrier (with backoff) ----
        __syncthreads();
        unsigned tgt = base + (unsigned)(n + 1);
        if (tid == 0) {
            asm volatile("st.release.gpu.global.u32 [%0], %1;"
                         :: "l"(myflag), "r"(tgt) : "memory");
        }
        if (tid < 64) {
            unsigned v;
            asm volatile("ld.acquire.gpu.global.u32 %0, [%1];"
                         : "=r"(v) : "l"(pollflag) : "memory");
            while ((int)(v - tgt) < 0) {
                __nanosleep(64);
                asm volatile("ld.acquire.gpu.global.u32 %0, [%1];"
                             : "=r"(v) : "l"(pollflag) : "memory");
            }
        }
        __syncthreads();
    }
}

// ==================================================================
// Kernel 3: epilogue
// ==================================================================
__global__ void __launch_bounds__(64)
epilogue_kernel(const int* __restrict__ yv,
                const float* __restrict__ wcl, const float* __restrict__ bcl,
                const float* __restrict__ wcr, const float* __restrict__ bcr,
                const float* __restrict__ Wout, const float* __restrict__ bout,
                float* __restrict__ out)
{
    __shared__ float lsum[64];
    const int b = threadIdx.x;

    float hl[HH + 2], hr[HH + 2], y3[HH];
    hl[0] = 0.0f; hl[HH + 1] = 0.0f;
    hr[0] = 0.0f; hr[HH + 1] = 0.0f;
    for (int j = 0; j < HH; ++j) {
        hl[j + 1] = g_hf[0][j][b];
        hr[j + 1] = g_hf[1][j][b];
    }
    float wl0 = wcl[0], wl1 = wcl[1], wl2 = wcl[2], bl = bcl[0];
    float wr0 = wcr[0], wr1 = wcr[1], wr2 = wcr[2], br_ = bcr[0];
    for (int j = 0; j < HH; ++j) {
        float vl = wl0 * hl[j] + wl1 * hl[j + 1] + wl2 * hl[j + 2] + bl;
        float vr = wr0 * hr[j] + wr1 * hr[j + 1] + wr2 * hr[j + 2] + br_;
        y3[j] = vl + vr;
        out[ACT_OFF + b * HH + j] = tanhf(y3[j]) * 0.1f;
    }
    float logits[LL];
    float mx = -1e30f;
    for (int l = 0; l < LL; ++l) {
        float s = bout[l];
        for (int j = 0; j < HH; ++j) s += y3[j] * Wout[l * HH + j];
        logits[l] = s;
        mx = fmaxf(mx, s);
    }
    float den = 0.0f;
    for (int l = 0; l < LL; ++l) { logits[l] = expf(logits[l] - mx); den += logits[l]; }
    float inv = 1.0f / den;
    int yb = yv[b];
    float py = 0.0f, myloss = 0.0f;
    for (int l = 0; l < LL; ++l) {
        float p = logits[l] * inv;
        logits[l] = p;
        out[PRED_OFF + b * LL + l] = p;
        if (l == yb) py = p;
    }
    for (int l = 0; l < LL; ++l) {
        float p = logits[l];
        float lp = fmaxf(logf(p), -100.0f);
        float lq = fmaxf(logf(1.0f - p), -100.0f);
        myloss += (l == yb) ? lp : lq;
    }
    int rank = 0;
    for (int l = 0; l < LL; ++l) {
        if (logits[l] > py) rank++;
        else if (logits[l] == py && l < yb) rank++;
    }
    out[ACC1_OFF + b] = (rank == 0) ? 1.0f : 0.0f;
    out[ACC3_OFF + b] = (rank < 3) ? 1.0f : 0.0f;

    lsum[b] = myloss;
    __syncthreads();
    if (b == 0) {
        float s = 0.0f;
        for (int i = 0; i < BATCH; ++i) s += lsum[i];
        out[0] = -s / (float)(BATCH * LL);
    }
}

// ==================================================================
extern "C" void kernel_launch(void* const* d_in, const int* in_sizes, int n_in,
                              void* d_out, int out_size) {
    (void)in_sizes; (void)n_in; (void)out_size;
    cudaFuncSetAttribute(pre_gemm_kernel, cudaFuncAttributeMaxDynamicSharedMemorySize,
                         GEMM_SMEM_FLOATS * (int)sizeof(float));
    cudaFuncSetAttribute(lstm_recurrent_kernel, cudaFuncAttributeMaxDynamicSharedMemorySize,
                         REC_SMEM_FLOATS * (int)sizeof(float));

    const float* xl  = (const float*)d_in[0];
    const float* xr  = (const float*)d_in[1];
    const float* xo  = (const float*)d_in[2];
    const int*   yv  = (const int*)d_in[3];
    const int*   isl = (const int*)d_in[4];
    const int*   isr = (const int*)d_in[5];
    const int*   dur = (const int*)d_in[6];

    pre_gemm_kernel<<<dim3(8, TT, 2), 128, GEMM_SMEM_FLOATS * sizeof(float)>>>(
        xl, xr, xo, isl, isr,
        (const float*)d_in[7],  (const float*)d_in[9],  (const float*)d_in[10],
        (const float*)d_in[15], (const float*)d_in[17], (const float*)d_in[18]);

    lstm_recurrent_kernel<<<128, 128, REC_SMEM_FLOATS * sizeof(float)>>>(
        (const float*)d_in[8],  (const float*)d_in[16],
        (const float*)d_in[11], (const float*)d_in[12],
        (const float*)d_in[13], (const float*)d_in[14],
        (const float*)d_in[19], (const float*)d_in[20],
        (const float*)d_in[21], (const float*)d_in[22],
        dur);

    epilogue_kernel<<<1, 64>>>(
        yv,
        (const float*)d_in[23], (const float*)d_in[24],
        (const float*)d_in[25], (const float*)d_in[26],
        (const float*)d_in[27], (const float*)d_in[28],
        (float*)d_out);
}

// round 6
// speedup vs baseline: 5.0578x; 2.0267x over previous
#include <cuda_runtime.h>
#include <math.h>
#include <stdint.h>

#define BATCH 64
#define TT    2048
#define HH    128
#define DIN   108
#define LL    37

#define BG    4      // batches per cluster
#define CSZ   4      // CTAs per cluster
#define UPC   32     // hidden units per CTA

#define ACC1_OFF 1
#define ACC3_OFF 65
#define ACT_OFF  129
#define PRED_OFF (129 + BATCH*HH)

// ---------------- device scratch (static; no runtime allocation) ----------------
__device__ __align__(16) float g_pre[2][TT][512][BATCH];   // x@Wih0^T + (bih0+bhh0)
__device__ __align__(16) float g_hf[2][HH][BATCH];

__device__ __forceinline__ float sigf(float x)    { return 1.0f / (1.0f + __expf(-x)); }
__device__ __forceinline__ float tanhfast(float x){ return 2.0f / (1.0f + __expf(-2.0f * x)) - 1.0f; }

__device__ __forceinline__ unsigned long long pack2(float x, float y) {
    unsigned long long r;
    asm("mov.b64 %0, {%1, %2};" : "=l"(r) : "f"(x), "f"(y));
    return r;
}
__device__ __forceinline__ void fma2(unsigned long long& acc, unsigned long long w2,
                                     unsigned long long v2) {
    asm("fma.rn.f32x2 %0, %1, %2, %0;" : "+l"(acc) : "l"(w2), "l"(v2));
}
__device__ __forceinline__ void unpack2(unsigned long long p, float& x, float& y) {
    asm("mov.b64 {%0, %1}, %2;" : "=f"(x), "=f"(y) : "l"(p));
}
__device__ __forceinline__ void st_cluster_f32(uint32_t saddr, uint32_t rk, float v) {
    uint32_t ra;
    asm volatile("mapa.shared::cluster.u32 %0, %1, %2;" : "=r"(ra) : "r"(saddr), "r"(rk));
    asm volatile("st.shared::cluster.f32 [%0], %1;" :: "r"(ra), "f"(v) : "memory");
}
#define CLUSTER_SYNC() do { \
    asm volatile("barrier.cluster.arrive.aligned;" ::: "memory"); \
    asm volatile("barrier.cluster.wait.aligned;"   ::: "memory"); \
} while (0)

// ==================================================================
// Kernel 1: precompute gate inputs  pre[br][t][row][b]
// ==================================================================
#define GX_XS 0
#define GX_WS (DIN*68)
#define GX_BS (GX_WS + 64*113)
#define GEMM_SMEM_FLOATS (GX_BS + 64)

__global__ void __launch_bounds__(128)
pre_gemm_kernel(const float* __restrict__ xl, const float* __restrict__ xr,
                const float* __restrict__ xo,
                const int* __restrict__ isl, const int* __restrict__ isr,
                const float* __restrict__ Wl, const float* __restrict__ bil, const float* __restrict__ bhl,
                const float* __restrict__ Wr, const float* __restrict__ bir, const float* __restrict__ bhr)
{
    extern __shared__ float sg[];
    float* xs  = sg + GX_XS;   // [k][68]
    float* Wsm = sg + GX_WS;   // [lr][113]
    float* bsm = sg + GX_BS;   // [64]

    const int rb  = blockIdx.x;
    const int t   = blockIdx.y;
    const int br  = blockIdx.z;
    const int tid = threadIdx.x;

    const float* xh  = br ? xr  : xl;
    const int*   ish = br ? isr : isl;
    const float* W   = br ? Wr  : Wl;
    const float* bi  = br ? bir : bil;
    const float* bh  = br ? bhr : bhl;

    for (int i = tid; i < BATCH * DIN; i += 128) {
        int b = i / DIN, k = i - b * DIN;
        float v;
        if (k < 99) v = xh[(b * TT + t) * 99 + k] * ((ish[b] != 0) ? 1.0f : 0.0f);
        else        v = xo[(b * TT + t) * 9 + (k - 99)];
        xs[k * 68 + b] = v;
    }
    for (int i = tid; i < 64 * DIN; i += 128) {
        int lr = i / DIN, k = i - lr * DIN;
        Wsm[lr * 113 + k] = W[(rb * 64 + lr) * DIN + k];
    }
    if (tid < 64) bsm[tid] = bi[rb * 64 + tid] + bh[rb * 64 + tid];
    __syncthreads();

    const int rg = tid >> 4;
    const int b4 = (tid & 15) * 4;

    float4 acc[8];
    #pragma unroll
    for (int j = 0; j < 8; ++j) {
        float bb = bsm[rg * 8 + j];
        acc[j] = make_float4(bb, bb, bb, bb);
    }
    #pragma unroll 4
    for (int k = 0; k < DIN; ++k) {
        float4 xv = *(const float4*)&xs[k * 68 + b4];
        #pragma unroll
        for (int j = 0; j < 8; ++j) {
            float w = Wsm[(rg * 8 + j) * 113 + k];
            acc[j].x += w * xv.x; acc[j].y += w * xv.y;
            acc[j].z += w * xv.z; acc[j].w += w * xv.w;
        }
    }
    #pragma unroll
    for (int j = 0; j < 8; ++j) {
        int row = rb * 64 + rg * 8 + j;
        *(float4*)&g_pre[br][t][row][b4] = acc[j];
    }
}

// ==================================================================
// Kernel 2: cluster-parallel wavefront recurrence.
// 128 CTAs = 2 branches x 16 batch-groups x 4-CTA clusters.
// Each CTA: 32 hidden units (L0 + L1) for 4 batches; weights in SMEM;
// h slices exchanged via DSMEM; only cluster barriers (no global sync).
// Interval s: L0 step s (threads 0-127), L1 step s-1 (threads 128-255).
// ==================================================================
#define W0_OFF  0                       // 128x128 (w0[k*128+r])
#define W1A_OFF (W0_OFF  + HH*HH)       // 128x128
#define W1B_OFF (W1A_OFF + HH*HH)       // 128x128
#define B1_OFF  (W1B_OFF + HH*HH)       // 128
#define H0B_OFF (B1_OFF  + HH)          // 2 slots x 128 units x BG
#define H2B_OFF (H0B_OFF + 2*HH*BG)
#define G0_OFF  (H2B_OFF + 2*HH*BG)     // 128 x BG
#define G1_OFF  (G0_OFF  + HH*BG)
#define REC_SMEM_FLOATS (G1_OFF + HH*BG)   // 52352 floats = 209408 B

__global__ void __launch_bounds__(256, 1) __cluster_dims__(CSZ, 1, 1)
lstm_recurrent_kernel(const float* __restrict__ Whh0_l, const float* __restrict__ Whh0_r,
                      const float* __restrict__ Wih1_l, const float* __restrict__ Whh1_l,
                      const float* __restrict__ bih1_l, const float* __restrict__ bhh1_l,
                      const float* __restrict__ Wih1_r, const float* __restrict__ Whh1_r,
                      const float* __restrict__ bih1_r, const float* __restrict__ bhh1_r,
                      const int* __restrict__ dur)
{
    extern __shared__ float sm[];
    float* w0   = sm + W0_OFF;
    float* w1a  = sm + W1A_OFF;
    float* w1b  = sm + W1B_OFF;
    float* b1sm = sm + B1_OFF;
    float* h0buf = sm + H0B_OFF;   // [slot][unit][b]
    float* h2buf = sm + H2B_OFF;
    float* g0f  = sm + G0_OFF;     // [row][b]
    float* g1f  = sm + G1_OFF;

    const int tid = threadIdx.x;
    const int blk = blockIdx.x;
    const int cid = blk >> 2;            // cluster id 0..31
    const int br  = cid >> 4;            // branch
    const int bg0 = (cid & 15) * BG;     // first batch of group

    uint32_t rank;
    asm("mov.u32 %0, %%cluster_ctarank;" : "=r"(rank));
    const int cu0 = (int)rank * UPC;     // first hidden unit owned by this CTA

    const float* Whh0 = br ? Whh0_r : Whh0_l;
    const float* Wih1 = br ? Wih1_r : Wih1_l;
    const float* Whh1 = br ? Whh1_r : Whh1_l;
    const float* bi1  = br ? bih1_r : bih1_l;
    const float* bh1  = br ? bhh1_r : bhh1_l;

    // ---- load weight slices: local row r = gate*32 + uloc -> grow = gate*128 + cu0 + uloc
    for (int i = tid; i < HH * HH; i += 256) {
        int r = i & 127, k = i >> 7;
        int grow = (r >> 5) * HH + cu0 + (r & 31);
        w0[k * 128 + r]  = Whh0[grow * HH + k];
        w1a[k * 128 + r] = Wih1[grow * HH + k];
        w1b[k * 128 + r] = Whh1[grow * HH + k];
    }
    if (tid < 128) {
        int grow = (tid >> 5) * HH + cu0 + (tid & 31);
        b1sm[tid] = bi1[grow] + bh1[grow];
    }
    for (int i = tid; i < 4 * HH * BG; i += 256) {   // zero both slots of both bufs
        h0buf[i >= 2 * HH * BG ? 0 : i] = 0.0f;      // (avoid OOB trick below)
    }
    // simpler explicit zeroing:
    for (int i = tid; i < 2 * HH * BG; i += 256) { h0buf[i] = 0.0f; h2buf[i] = 0.0f; }
    __syncthreads();
    CLUSTER_SYNC();   // zeros visible before any peer writes

    const bool isL0 = (tid < 128);
    const int  r    = isL0 ? tid : tid - 128;          // gate row 0..127
    const int  grow = (r >> 5) * HH + cu0 + (r & 31);  // global gate row
    const int  s_uloc = r & 31;                        // state-update mapping
    const int  s_b    = r >> 5;                        // 0..3
    float c0 = 0.0f, c1 = 0.0f;
    const int durb = dur[bg0 + s_b];

    float4 p = make_float4(0.f, 0.f, 0.f, 0.f);
    if (isL0) p = __ldcs((const float4*)&g_pre[br][0][grow][bg0]);

    const uint32_t h0base = (uint32_t)__cvta_generic_to_shared(h0buf);
    const uint32_t h2base = (uint32_t)__cvta_generic_to_shared(h2buf);

    for (int s = 0; s <= TT; ++s) {
        const float* h0prev = h0buf + ((s + 1) & 1) * (HH * BG);
        const float* h2prev = h2buf + ((s + 1) & 1) * (HH * BG);

        if (isL0) {
            if (s < TT) {
                unsigned long long a01 = pack2(p.x, p.y);
                unsigned long long a23 = pack2(p.z, p.w);
                if (s + 1 < TT)
                    p = __ldcs((const float4*)&g_pre[br][s + 1][grow][bg0]);
                #pragma unroll 8
                for (int k = 0; k < HH; ++k) {
                    float w = w0[k * 128 + r];
                    unsigned long long wp = pack2(w, w);
                    ulonglong2 v = *(const ulonglong2*)&h0prev[k * BG];
                    fma2(a01, wp, v.x);
                    fma2(a23, wp, v.y);
                }
                ((ulonglong2*)g0f)[r] = make_ulonglong2(a01, a23);
            }
        } else {
            if (s >= 1) {
                float bb = b1sm[r];
                unsigned long long a01 = pack2(bb, bb), a23 = a01;
                #pragma unroll 8
                for (int k = 0; k < HH; ++k) {
                    float w = w1a[k * 128 + r];
                    unsigned long long wp = pack2(w, w);
                    ulonglong2 v = *(const ulonglong2*)&h0prev[k * BG];
                    fma2(a01, wp, v.x);
                    fma2(a23, wp, v.y);
                }
                #pragma unroll 8
                for (int k = 0; k < HH; ++k) {
                    float w = w1b[k * 128 + r];
                    unsigned long long wp = pack2(w, w);
                    ulonglong2 v = *(const ulonglong2*)&h2prev[k * BG];
                    fma2(a01, wp, v.x);
                    fma2(a23, wp, v.y);
                }
                ((ulonglong2*)g1f)[r] = make_ulonglong2(a01, a23);
            }
        }
        __syncthreads();

        // ---- state update + DSMEM broadcast of h slices ----
        if (isL0) {
            if (s < TT) {
                float ip = g0f[(0  + s_uloc) * BG + s_b];
                float fp = g0f[(32 + s_uloc) * BG + s_b];
                float gp = g0f[(64 + s_uloc) * BG + s_b];
                float op = g0f[(96 + s_uloc) * BG + s_b];
                c0 = sigf(fp) * c0 + sigf(ip) * tanhfast(gp);
                float h = sigf(op) * tanhfast(c0);
                uint32_t la = h0base + (uint32_t)(((s & 1) * (HH * BG)
                             + (cu0 + s_uloc) * BG + s_b) * 4);
                #pragma unroll
                for (uint32_t rr = 0; rr < CSZ; ++rr) st_cluster_f32(la, rr, h);
            }
        } else {
            if (s >= 1) {
                float ip = g1f[(0  + s_uloc) * BG + s_b];
                float fp = g1f[(32 + s_uloc) * BG + s_b];
                float gp = g1f[(64 + s_uloc) * BG + s_b];
                float op = g1f[(96 + s_uloc) * BG + s_b];
                c1 = sigf(fp) * c1 + sigf(ip) * tanhfast(gp);
                float h = sigf(op) * tanhfast(c1);
                uint32_t la = h2base + (uint32_t)(((s & 1) * (HH * BG)
                             + (cu0 + s_uloc) * BG + s_b) * 4);
                #pragma unroll
                for (uint32_t rr = 0; rr < CSZ; ++rr) st_cluster_f32(la, rr, h);
                if (s - 1 == durb - 1)
                    g_hf[br][cu0 + s_uloc][bg0 + s_b] = h;
            }
        }
        CLUSTER_SYNC();   // release my DSMEM writes; wait for peers'
    }
}

// ==================================================================
// Kernel 3: epilogue
// ==================================================================
__global__ void __launch_bounds__(64)
epilogue_kernel(const int* __restrict__ yv,
                const float* __restrict__ wcl, const float* __restrict__ bcl,
                const float* __restrict__ wcr, const float* __restrict__ bcr,
                const float* __restrict__ Wout, const float* __restrict__ bout,
                float* __restrict__ out)
{
    __shared__ float lsum[64];
    const int b = threadIdx.x;

    float hl[HH + 2], hr[HH + 2], y3[HH];
    hl[0] = 0.0f; hl[HH + 1] = 0.0f;
    hr[0] = 0.0f; hr[HH + 1] = 0.0f;
    for (int j = 0; j < HH; ++j) {
        hl[j + 1] = g_hf[0][j][b];
        hr[j + 1] = g_hf[1][j][b];
    }
    float wl0 = wcl[0], wl1 = wcl[1], wl2 = wcl[2], bl = bcl[0];
    float wr0 = wcr[0], wr1 = wcr[1], wr2 = wcr[2], br_ = bcr[0];
    for (int j = 0; j < HH; ++j) {
        float vl = wl0 * hl[j] + wl1 * hl[j + 1] + wl2 * hl[j + 2] + bl;
        float vr = wr0 * hr[j] + wr1 * hr[j + 1] + wr2 * hr[j + 2] + br_;
        y3[j] = vl + vr;
        out[ACT_OFF + b * HH + j] = tanhf(y3[j]) * 0.1f;
    }
    float logits[LL];
    float mx = -1e30f;
    for (int l = 0; l < LL; ++l) {
        float s = bout[l];
        for (int j = 0; j < HH; ++j) s += y3[j] * Wout[l * HH + j];
        logits[l] = s;
        mx = fmaxf(mx, s);
    }
    float den = 0.0f;
    for (int l = 0; l < LL; ++l) { logits[l] = expf(logits[l] - mx); den += logits[l]; }
    float inv = 1.0f / den;
    int yb = yv[b];
    float py = 0.0f, myloss = 0.0f;
    for (int l = 0; l < LL; ++l) {
        float pql = logits[l] * inv;
        logits[l] = pql;
        out[PRED_OFF + b * LL + l] = pql;
        if (l == yb) py = pql;
    }
    for (int l = 0; l < LL; ++l) {
        float pql = logits[l];
        float lp = fmaxf(logf(pql), -100.0f);
        float lq = fmaxf(logf(1.0f - pql), -100.0f);
        myloss += (l == yb) ? lp : lq;
    }
    int rank = 0;
    for (int l = 0; l < LL; ++l) {
        if (logits[l] > py) rank++;
        else if (logits[l] == py && l < yb) rank++;
    }
    out[ACC1_OFF + b] = (rank == 0) ? 1.0f : 0.0f;
    out[ACC3_OFF + b] = (rank < 3) ? 1.0f : 0.0f;

    lsum[b] = myloss;
    __syncthreads();
    if (b == 0) {
        float s = 0.0f;
        for (int i = 0; i < BATCH; ++i) s += lsum[i];
        out[0] = -s / (float)(BATCH * LL);
    }
}

// ==================================================================
extern "C" void kernel_launch(void* const* d_in, const int* in_sizes, int n_in,
                              void* d_out, int out_size) {
    (void)in_sizes; (void)n_in; (void)out_size;
    cudaFuncSetAttribute(pre_gemm_kernel, cudaFuncAttributeMaxDynamicSharedMemorySize,
                         GEMM_SMEM_FLOATS * (int)sizeof(float));
    cudaFuncSetAttribute(lstm_recurrent_kernel, cudaFuncAttributeMaxDynamicSharedMemorySize,
                         REC_SMEM_FLOATS * (int)sizeof(float));

    const float* xl  = (const float*)d_in[0];
    const float* xr  = (const float*)d_in[1];
    const float* xo  = (const float*)d_in[2];
    const int*   yv  = (const int*)d_in[3];
    const int*   isl = (const int*)d_in[4];
    const int*   isr = (const int*)d_in[5];
    const int*   dur = (const int*)d_in[6];

    pre_gemm_kernel<<<dim3(8, TT, 2), 128, GEMM_SMEM_FLOATS * sizeof(float)>>>(
        xl, xr, xo, isl, isr,
        (const float*)d_in[7],  (const float*)d_in[9],  (const float*)d_in[10],
        (const float*)d_in[15], (const float*)d_in[17], (const float*)d_in[18]);

    lstm_recurrent_kernel<<<128, 256, REC_SMEM_FLOATS * sizeof(float)>>>(
        (const float*)d_in[8],  (const float*)d_in[16],
        (const float*)d_in[11], (const float*)d_in[12],
        (const float*)d_in[13], (const float*)d_in[14],
        (const float*)d_in[19], (const float*)d_in[20],
        (const float*)d_in[21], (const float*)d_in[22],
        dur);

    epilogue_kernel<<<1, 64>>>(
        yv,
        (const float*)d_in[23], (const float*)d_in[24],
        (const float*)d_in[25], (const float*)d_in[26],
        (const float*)d_in[27], (const float*)d_in[28],
        (float*)d_out);
}

// round 8
// speedup vs baseline: 6.9676x; 1.3776x over previous
#include <cuda_runtime.h>
#include <math.h>
#include <stdint.h>

#define BATCH 64
#define TT    2048
#define HH    128
#define DIN   108
#define LL    37

#define BG    4      // batches per cluster
#define CSZ   4      // CTAs per cluster
#define UPC   32     // hidden units per CTA

#define ACC1_OFF 1
#define ACC3_OFF 65
#define ACT_OFF  129
#define PRED_OFF (129 + BATCH*HH)

// ---------------- device scratch (static; no runtime allocation) ----------------
__device__ __align__(16) float g_pre[2][TT][512][BATCH];   // x@Wih0^T + (bih0+bhh0)
__device__ __align__(16) float g_hf[2][HH][BATCH];

__device__ __forceinline__ float sigf(float x)    { return 1.0f / (1.0f + __expf(-x)); }
__device__ __forceinline__ float tanhfast(float x){ return 2.0f / (1.0f + __expf(-2.0f * x)) - 1.0f; }

__device__ __forceinline__ unsigned long long pack2(float x, float y) {
    unsigned long long r;
    asm("mov.b64 %0, {%1, %2};" : "=l"(r) : "f"(x), "f"(y));
    return r;
}
__device__ __forceinline__ void fma2(unsigned long long& acc, unsigned long long w2,
                                     unsigned long long v2) {
    asm("fma.rn.f32x2 %0, %1, %2, %0;" : "+l"(acc) : "l"(w2), "l"(v2));
}
__device__ __forceinline__ void st_cluster_f32(uint32_t saddr, uint32_t rk, float v) {
    uint32_t ra;
    asm volatile("mapa.shared::cluster.u32 %0, %1, %2;" : "=r"(ra) : "r"(saddr), "r"(rk));
    asm volatile("st.shared::cluster.f32 [%0], %1;" :: "r"(ra), "f"(v) : "memory");
}
#define CLUSTER_SYNC() do { \
    asm volatile("barrier.cluster.arrive.aligned;" ::: "memory"); \
    asm volatile("barrier.cluster.wait.aligned;"   ::: "memory"); \
} while (0)

// ==================================================================
// Kernel 1: precompute gate inputs  pre[br][t][row][b]
// ==================================================================
#define GX_XS 0
#define GX_WS (DIN*68)
#define GX_BS (GX_WS + 64*113)
#define GEMM_SMEM_FLOATS (GX_BS + 64)

__global__ void __launch_bounds__(128)
pre_gemm_kernel(const float* __restrict__ xl, const float* __restrict__ xr,
                const float* __restrict__ xo,
                const int* __restrict__ isl, const int* __restrict__ isr,
                const float* __restrict__ Wl, const float* __restrict__ bil, const float* __restrict__ bhl,
                const float* __restrict__ Wr, const float* __restrict__ bir, const float* __restrict__ bhr)
{
    extern __shared__ float sg[];
    float* xs  = sg + GX_XS;
    float* Wsm = sg + GX_WS;
    float* bsm = sg + GX_BS;

    const int rb  = blockIdx.x;
    const int t   = blockIdx.y;
    const int br  = blockIdx.z;
    const int tid = threadIdx.x;

    const float* xh  = br ? xr  : xl;
    const int*   ish = br ? isr : isl;
    const float* W   = br ? Wr  : Wl;
    const float* bi  = br ? bir : bil;
    const float* bh  = br ? bhr : bhl;

    for (int i = tid; i < BATCH * DIN; i += 128) {
        int b = i / DIN, k = i - b * DIN;
        float v;
        if (k < 99) v = xh[(b * TT + t) * 99 + k] * ((ish[b] != 0) ? 1.0f : 0.0f);
        else        v = xo[(b * TT + t) * 9 + (k - 99)];
        xs[k * 68 + b] = v;
    }
    for (int i = tid; i < 64 * DIN; i += 128) {
        int lr = i / DIN, k = i - lr * DIN;
        Wsm[lr * 113 + k] = W[(rb * 64 + lr) * DIN + k];
    }
    if (tid < 64) bsm[tid] = bi[rb * 64 + tid] + bh[rb * 64 + tid];
    __syncthreads();

    const int rg = tid >> 4;
    const int b4 = (tid & 15) * 4;

    float4 acc[8];
    #pragma unroll
    for (int j = 0; j < 8; ++j) {
        float bb = bsm[rg * 8 + j];
        acc[j] = make_float4(bb, bb, bb, bb);
    }
    #pragma unroll 4
    for (int k = 0; k < DIN; ++k) {
        float4 xv = *(const float4*)&xs[k * 68 + b4];
        #pragma unroll
        for (int j = 0; j < 8; ++j) {
            float w = Wsm[(rg * 8 + j) * 113 + k];
            acc[j].x += w * xv.x; acc[j].y += w * xv.y;
            acc[j].z += w * xv.z; acc[j].w += w * xv.w;
        }
    }
    #pragma unroll
    for (int j = 0; j < 8; ++j) {
        int row = rb * 64 + rg * 8 + j;
        *(float4*)&g_pre[br][t][row][b4] = acc[j];
    }
}

// ==================================================================
// Kernel 2: cluster-parallel wavefront recurrence, balanced 3-job split.
// 128 CTAs = 2 branches x 16 batch-groups x 4-CTA clusters.
// 384 threads: jid0 = L0 (Whh0), jid1 = L1 (Wih1), jid2 = L1 (Whh1);
// every thread does exactly 128 k-iterations per interval.
// k in [0,64): register-resident weights; k in [64,128): SMEM.
// Sync: barrier.cluster (proven in R6). h exchanged via DSMEM stores.
// ==================================================================
#define WS_OFF  0                        // ws[3][64][128] (high-k halves)
#define B1_OFF  (WS_OFF + 3*64*HH)       // 128
#define H0_OFF  (B1_OFF + HH)            // 2 slots x 128 units x 4
#define H2_OFF  (H0_OFF + 2*HH*BG)
#define G_OFF   (H2_OFF + 2*HH*BG)       // g[3][128][4]
#define REC_SMEM_FLOATS (G_OFF + 3*HH*BG)   // 28288 floats = 113152 B

__global__ void __launch_bounds__(384, 1) __cluster_dims__(CSZ, 1, 1)
lstm_recurrent_kernel(const float* __restrict__ Whh0_l, const float* __restrict__ Whh0_r,
                      const float* __restrict__ Wih1_l, const float* __restrict__ Whh1_l,
                      const float* __restrict__ bih1_l, const float* __restrict__ bhh1_l,
                      const float* __restrict__ Wih1_r, const float* __restrict__ Whh1_r,
                      const float* __restrict__ bih1_r, const float* __restrict__ bhh1_r,
                      const int* __restrict__ dur)
{
    extern __shared__ float sm[];
    float* wsAll = sm + WS_OFF;
    float* b1sm  = sm + B1_OFF;
    float* h0buf = sm + H0_OFF;    // [slot][unit(128)][b(4)]
    float* h2buf = sm + H2_OFF;
    float* gall  = sm + G_OFF;     // [jid][row(128)][b(4)]

    const int tid = threadIdx.x;
    const int blk = blockIdx.x;
    const int cid = blk >> 2;            // cluster id 0..31
    const int br  = cid >> 4;            // branch
    const int bg0 = (cid & 15) * BG;     // first batch of group

    uint32_t rank;
    asm("mov.u32 %0, %%cluster_ctarank;" : "=r"(rank));
    const int cu0 = (int)rank * UPC;

    const float* Whh0 = br ? Whh0_r : Whh0_l;
    const float* Wih1 = br ? Wih1_r : Wih1_l;
    const float* Whh1 = br ? Whh1_r : Whh1_l;
    const float* bi1  = br ? bih1_r : bih1_l;
    const float* bh1  = br ? bhh1_r : bhh1_l;

    const int jid = tid >> 7;            // 0=L0, 1=L1a(Wih1), 2=L1b(Whh1)
    const int r   = tid & 127;           // gate-row: gate = r>>5, uloc = r&31
    const int grow = (r >> 5) * HH + cu0 + (r & 31);

    const float* mat = (jid == 0) ? Whh0 : ((jid == 1) ? Wih1 : Whh1);

    // ---- weights: k [0,64) -> registers; k [64,128) -> smem [kk][r] ----
    float wreg[64];
    #pragma unroll
    for (int k = 0; k < 64; ++k) wreg[k] = mat[grow * HH + k];
    float* wsm = wsAll + jid * 64 * HH;
    for (int kk = 0; kk < 64; ++kk) wsm[kk * HH + r] = mat[grow * HH + 64 + kk];

    if (tid < HH) {
        int gr = (tid >> 5) * HH + cu0 + (tid & 31);
        b1sm[tid] = bi1[gr] + bh1[gr];
    }
    for (int i = tid; i < 2 * HH * BG; i += 384) { h0buf[i] = 0.0f; h2buf[i] = 0.0f; }
    __syncthreads();
    CLUSTER_SYNC();   // zeros + smem weights visible cluster-wide before first step

    const uint32_t h0base = (uint32_t)__cvta_generic_to_shared(h0buf);
    const uint32_t h2base = (uint32_t)__cvta_generic_to_shared(h2buf);

    // state-update identity (threads 0..255): unit su, batch sb
    const int su = (tid & 127) >> 2;
    const int sb = tid & 3;
    float c0 = 0.0f, c1 = 0.0f;
    const int durb = dur[bg0 + sb];

    float4 p = make_float4(0.f, 0.f, 0.f, 0.f);
    if (jid == 0) p = __ldcs((const float4*)&g_pre[br][0][grow][bg0]);

    for (int s = 0; s <= TT; ++s) {
        const float* h0prev = h0buf + ((s + 1) & 1) * (HH * BG);
        const float* h2prev = h2buf + ((s + 1) & 1) * (HH * BG);

        // ---- gate partial loops (balanced: every active thread 128 k) ----
        const bool active = (jid == 0) ? (s < TT) : (s >= 1);
        if (active) {
            unsigned long long a01, a23;
            if (jid == 0) {
                a01 = pack2(p.x, p.y); a23 = pack2(p.z, p.w);
                if (s + 1 < TT)
                    p = __ldcs((const float4*)&g_pre[br][s + 1][grow][bg0]);
            } else if (jid == 1) {
                float bb = b1sm[r];
                a01 = pack2(bb, bb); a23 = a01;
            } else {
                a01 = 0ull; a23 = 0ull;
            }
            const float* hsrc = (jid == 2) ? h2prev : h0prev;
            #pragma unroll
            for (int k = 0; k < 64; ++k) {
                ulonglong2 v = *(const ulonglong2*)&hsrc[k * BG];
                unsigned long long wp = pack2(wreg[k], wreg[k]);
                fma2(a01, wp, v.x);
                fma2(a23, wp, v.y);
            }
            #pragma unroll 8
            for (int kk = 0; kk < 64; ++kk) {
                float w = wsm[kk * HH + r];
                unsigned long long wp = pack2(w, w);
                ulonglong2 v = *(const ulonglong2*)&hsrc[(64 + kk) * BG];
                fma2(a01, wp, v.x);
                fma2(a23, wp, v.y);
            }
            ((ulonglong2*)gall)[jid * HH + r] = make_ulonglong2(a01, a23);
        }
        __syncthreads();

        // ---- state updates + DSMEM broadcast ----
        if (tid < 128) {
            if (s < TT) {
                const float* g0 = gall;
                float ip = g0[(0  + su) * BG + sb];
                float fp = g0[(32 + su) * BG + sb];
                float gp = g0[(64 + su) * BG + sb];
                float op = g0[(96 + su) * BG + sb];
                c0 = sigf(fp) * c0 + sigf(ip) * tanhfast(gp);
                float h = sigf(op) * tanhfast(c0);
                uint32_t la = h0base + (uint32_t)((((s & 1) * HH + cu0 + su) * BG + sb) * 4);
                #pragma unroll
                for (uint32_t rr = 0; rr < CSZ; ++rr) st_cluster_f32(la, rr, h);
            }
        } else if (tid < 256) {
            if (s >= 1) {
                const float* ga = gall + 1 * HH * BG;
                const float* gb = gall + 2 * HH * BG;
                float ip = ga[(0  + su) * BG + sb] + gb[(0  + su) * BG + sb];
                float fp = ga[(32 + su) * BG + sb] + gb[(32 + su) * BG + sb];
                float gp = ga[(64 + su) * BG + sb] + gb[(64 + su) * BG + sb];
                float op = ga[(96 + su) * BG + sb] + gb[(96 + su) * BG + sb];
                c1 = sigf(fp) * c1 + sigf(ip) * tanhfast(gp);
                float h = sigf(op) * tanhfast(c1);
                uint32_t la = h2base + (uint32_t)((((s & 1) * HH + cu0 + su) * BG + sb) * 4);
                #pragma unroll
                for (uint32_t rr = 0; rr < CSZ; ++rr) st_cluster_f32(la, rr, h);
                if (s == durb) g_hf[br][cu0 + su][bg0 + sb] = h;
            }
        }
        CLUSTER_SYNC();   // release DSMEM writes; wait for peers
    }
}

// ==================================================================
// Kernel 3: epilogue
// ==================================================================
__global__ void __launch_bounds__(64)
epilogue_kernel(const int* __restrict__ yv,
                const float* __restrict__ wcl, const float* __restrict__ bcl,
                const float* __restrict__ wcr, const float* __restrict__ bcr,
                const float* __restrict__ Wout, const float* __restrict__ bout,
                float* __restrict__ out)
{
    __shared__ float lsum[64];
    const int b = threadIdx.x;

    float hl[HH + 2], hr[HH + 2], y3[HH];
    hl[0] = 0.0f; hl[HH + 1] = 0.0f;
    hr[0] = 0.0f; hr[HH + 1] = 0.0f;
    for (int j = 0; j < HH; ++j) {
        hl[j + 1] = g_hf[0][j][b];
        hr[j + 1] = g_hf[1][j][b];
    }
    float wl0 = wcl[0], wl1 = wcl[1], wl2 = wcl[2], bl = bcl[0];
    float wr0 = wcr[0], wr1 = wcr[1], wr2 = wcr[2], br_ = bcr[0];
    for (int j = 0; j < HH; ++j) {
        float vl = wl0 * hl[j] + wl1 * hl[j + 1] + wl2 * hl[j + 2] + bl;
        float vr = wr0 * hr[j] + wr1 * hr[j + 1] + wr2 * hr[j + 2] + br_;
        y3[j] = vl + vr;
        out[ACT_OFF + b * HH + j] = tanhf(y3[j]) * 0.1f;
    }
    float logits[LL];
    float mx = -1e30f;
    for (int l = 0; l < LL; ++l) {
        float s = bout[l];
        for (int j = 0; j < HH; ++j) s += y3[j] * Wout[l * HH + j];
        logits[l] = s;
        mx = fmaxf(mx, s);
    }
    float den = 0.0f;
    for (int l = 0; l < LL; ++l) { logits[l] = expf(logits[l] - mx); den += logits[l]; }
    float inv = 1.0f / den;
    int yb = yv[b];
    float py = 0.0f, myloss = 0.0f;
    for (int l = 0; l < LL; ++l) {
        float pql = logits[l] * inv;
        logits[l] = pql;
        out[PRED_OFF + b * LL + l] = pql;
        if (l == yb) py = pql;
    }
    for (int l = 0; l < LL; ++l) {
        float pql = logits[l];
        float lp = fmaxf(logf(pql), -100.0f);
        float lq = fmaxf(logf(1.0f - pql), -100.0f);
        myloss += (l == yb) ? lp : lq;
    }
    int rank = 0;
    for (int l = 0; l < LL; ++l) {
        if (logits[l] > py) rank++;
        else if (logits[l] == py && l < yb) rank++;
    }
    out[ACC1_OFF + b] = (rank == 0) ? 1.0f : 0.0f;
    out[ACC3_OFF + b] = (rank < 3) ? 1.0f : 0.0f;

    lsum[b] = myloss;
    __syncthreads();
    if (b == 0) {
        float s = 0.0f;
        for (int i = 0; i < BATCH; ++i) s += lsum[i];
        out[0] = -s / (float)(BATCH * LL);
    }
}

// ==================================================================
extern "C" void kernel_launch(void* const* d_in, const int* in_sizes, int n_in,
                              void* d_out, int out_size) {
    (void)in_sizes; (void)n_in; (void)out_size;
    cudaFuncSetAttribute(pre_gemm_kernel, cudaFuncAttributeMaxDynamicSharedMemorySize,
                         GEMM_SMEM_FLOATS * (int)sizeof(float));
    cudaFuncSetAttribute(lstm_recurrent_kernel, cudaFuncAttributeMaxDynamicSharedMemorySize,
                         REC_SMEM_FLOATS * (int)sizeof(float));

    const float* xl  = (const float*)d_in[0];
    const float* xr  = (const float*)d_in[1];
    const float* xo  = (const float*)d_in[2];
    const int*   yv  = (const int*)d_in[3];
    const int*   isl = (const int*)d_in[4];
    const int*   isr = (const int*)d_in[5];
    const int*   dur = (const int*)d_in[6];

    pre_gemm_kernel<<<dim3(8, TT, 2), 128, GEMM_SMEM_FLOATS * sizeof(float)>>>(
        xl, xr, xo, isl, isr,
        (const float*)d_in[7],  (const float*)d_in[9],  (const float*)d_in[10],
        (const float*)d_in[15], (const float*)d_in[17], (const float*)d_in[18]);

    lstm_recurrent_kernel<<<128, 384, REC_SMEM_FLOATS * sizeof(float)>>>(
        (const float*)d_in[8],  (const float*)d_in[16],
        (const float*)d_in[11], (const float*)d_in[12],
        (const float*)d_in[13], (const float*)d_in[14],
        (const float*)d_in[19], (const float*)d_in[20],
        (const float*)d_in[21], (const float*)d_in[22],
        dur);

    epilogue_kernel<<<1, 64>>>(
        yv,
        (const float*)d_in[23], (const float*)d_in[24],
        (const float*)d_in[25], (const float*)d_in[26],
        (const float*)d_in[27], (const float*)d_in[28],
        (float*)d_out);
}

// round 10
// speedup vs baseline: 7.3734x; 1.0582x over previous
#include <cuda_runtime.h>
#include <math.h>
#include <stdint.h>

#define BATCH 64
#define TT    2048
#define HH    128
#define DIN   108
#define LL    37

#define BG    4      // batches per cluster
#define CSZ   4      // CTAs per cluster
#define UPC   32     // hidden units per CTA

#define WREG  96     // k-range held in registers
#define WSMK  32     // k-range held in smem

#define ACC1_OFF 1
#define ACC3_OFF 65
#define ACT_OFF  129
#define PRED_OFF (129 + BATCH*HH)

// ---------------- device scratch (static; no runtime allocation) ----------------
__device__ __align__(16) float g_pre[2][TT][512][BATCH];   // x@Wih0^T + (bih0+bhh0)
__device__ __align__(16) float g_hf[2][HH][BATCH];

__device__ __forceinline__ float sigf(float x)    { return 1.0f / (1.0f + __expf(-x)); }
__device__ __forceinline__ float tanhfast(float x){ return 2.0f / (1.0f + __expf(-2.0f * x)) - 1.0f; }

__device__ __forceinline__ unsigned long long pack2(float x, float y) {
    unsigned long long r;
    asm("mov.b64 %0, {%1, %2};" : "=l"(r) : "f"(x), "f"(y));
    return r;
}
__device__ __forceinline__ void fma2(unsigned long long& acc, unsigned long long w2,
                                     unsigned long long v2) {
    asm("fma.rn.f32x2 %0, %1, %2, %0;" : "+l"(acc) : "l"(w2), "l"(v2));
}
__device__ __forceinline__ void st_cluster_f32(uint32_t saddr, uint32_t rk, float v) {
    uint32_t ra;
    asm volatile("mapa.shared::cluster.u32 %0, %1, %2;" : "=r"(ra) : "r"(saddr), "r"(rk));
    asm volatile("st.shared::cluster.f32 [%0], %1;" :: "r"(ra), "f"(v) : "memory");
}
#define CLUSTER_ARRIVE() asm volatile("barrier.cluster.arrive.aligned;" ::: "memory")
#define CLUSTER_WAIT()   asm volatile("barrier.cluster.wait.aligned;"   ::: "memory")
#define BAR_SYNC(id, cnt) asm volatile("bar.sync %0, %1;" :: "r"(id), "r"(cnt) : "memory")

// ==================================================================
// Kernel 1: precompute gate inputs  pre[br][t][row][b]
// ==================================================================
#define GX_XS 0
#define GX_WS (DIN*68)
#define GX_BS (GX_WS + 64*113)
#define GEMM_SMEM_FLOATS (GX_BS + 64)

__global__ void __launch_bounds__(128)
pre_gemm_kernel(const float* __restrict__ xl, const float* __restrict__ xr,
                const float* __restrict__ xo,
                const int* __restrict__ isl, const int* __restrict__ isr,
                const float* __restrict__ Wl, const float* __restrict__ bil, const float* __restrict__ bhl,
                const float* __restrict__ Wr, const float* __restrict__ bir, const float* __restrict__ bhr)
{
    extern __shared__ float sg[];
    float* xs  = sg + GX_XS;
    float* Wsm = sg + GX_WS;
    float* bsm = sg + GX_BS;

    const int rb  = blockIdx.x;
    const int t   = blockIdx.y;
    const int br  = blockIdx.z;
    const int tid = threadIdx.x;

    const float* xh  = br ? xr  : xl;
    const int*   ish = br ? isr : isl;
    const float* W   = br ? Wr  : Wl;
    const float* bi  = br ? bir : bil;
    const float* bh  = br ? bhr : bhl;

    for (int i = tid; i < BATCH * DIN; i += 128) {
        int b = i / DIN, k = i - b * DIN;
        float v;
        if (k < 99) v = xh[(b * TT + t) * 99 + k] * ((ish[b] != 0) ? 1.0f : 0.0f);
        else        v = xo[(b * TT + t) * 9 + (k - 99)];
        xs[k * 68 + b] = v;
    }
    for (int i = tid; i < 64 * DIN; i += 128) {
        int lr = i / DIN, k = i - lr * DIN;
        Wsm[lr * 113 + k] = W[(rb * 64 + lr) * DIN + k];
    }
    if (tid < 64) bsm[tid] = bi[rb * 64 + tid] + bh[rb * 64 + tid];
    __syncthreads();

    const int rg = tid >> 4;
    const int b4 = (tid & 15) * 4;

    float4 acc[8];
    #pragma unroll
    for (int j = 0; j < 8; ++j) {
        float bb = bsm[rg * 8 + j];
        acc[j] = make_float4(bb, bb, bb, bb);
    }
    #pragma unroll 4
    for (int k = 0; k < DIN; ++k) {
        float4 xv = *(const float4*)&xs[k * 68 + b4];
        #pragma unroll
        for (int j = 0; j < 8; ++j) {
            float w = Wsm[(rg * 8 + j) * 113 + k];
            acc[j].x += w * xv.x; acc[j].y += w * xv.y;
            acc[j].z += w * xv.z; acc[j].w += w * xv.w;
        }
    }
    #pragma unroll
    for (int j = 0; j < 8; ++j) {
        int row = rb * 64 + rg * 8 + j;
        *(float4*)&g_pre[br][t][row][b4] = acc[j];
    }
}

// ==================================================================
// Kernel 2: cluster-parallel wavefront recurrence, balanced 3-job split.
// 128 CTAs = 2 branches x 16 batch-groups x 4-CTA clusters.
// 384 threads: jid0 = L0 (Whh0), jid1 = L1 (Wih1), jid2 = L1 (Whh1).
// k in [0,96): register-resident weights; k in [96,128): SMEM.
// Mid-interval sync: named barriers (jid0 alone; jid1+jid2 together).
// Cluster sync split: arrive after stores, prefetch, then wait.
// ==================================================================
#define WS_OFF  0                        // ws[3][WSMK][128]
#define B1_OFF  (WS_OFF + 3*WSMK*HH)     // 128
#define H0_OFF  (B1_OFF + HH)            // 2 slots x 128 units x 4
#define H2_OFF  (H0_OFF + 2*HH*BG)
#define G_OFF   (H2_OFF + 2*HH*BG)       // g[3][128][4]
#define REC_SMEM_FLOATS (G_OFF + 3*HH*BG)   // 16000 floats = 64000 B

__global__ void __launch_bounds__(384, 1) __cluster_dims__(CSZ, 1, 1)
lstm_recurrent_kernel(const float* __restrict__ Whh0_l, const float* __restrict__ Whh0_r,
                      const float* __restrict__ Wih1_l, const float* __restrict__ Whh1_l,
                      const float* __restrict__ bih1_l, const float* __restrict__ bhh1_l,
                      const float* __restrict__ Wih1_r, const float* __restrict__ Whh1_r,
                      const float* __restrict__ bih1_r, const float* __restrict__ bhh1_r,
                      const int* __restrict__ dur)
{
    extern __shared__ float sm[];
    float* wsAll = sm + WS_OFF;
    float* b1sm  = sm + B1_OFF;
    float* h0buf = sm + H0_OFF;    // [slot][unit(128)][b(4)]
    float* h2buf = sm + H2_OFF;
    float* gall  = sm + G_OFF;     // [jid][row(128)][b(4)]

    const int tid = threadIdx.x;
    const int blk = blockIdx.x;
    const int cid = blk >> 2;            // cluster id 0..31
    const int br  = cid >> 4;            // branch
    const int bg0 = (cid & 15) * BG;     // first batch of group

    uint32_t rank;
    asm("mov.u32 %0, %%cluster_ctarank;" : "=r"(rank));
    const int cu0 = (int)rank * UPC;

    const float* Whh0 = br ? Whh0_r : Whh0_l;
    const float* Wih1 = br ? Wih1_r : Wih1_l;
    const float* Whh1 = br ? Whh1_r : Whh1_l;
    const float* bi1  = br ? bih1_r : bih1_l;
    const float* bh1  = br ? bhh1_r : bhh1_l;

    const int jid = tid >> 7;            // 0=L0, 1=L1a(Wih1), 2=L1b(Whh1)
    const int r   = tid & 127;           // gate-row: gate = r>>5, uloc = r&31
    const int grow = (r >> 5) * HH + cu0 + (r & 31);

    const float* mat = (jid == 0) ? Whh0 : ((jid == 1) ? Wih1 : Whh1);

    // ---- weights: k [0,WREG) -> registers; k [WREG,128) -> smem [kk][r] ----
    float wreg[WREG];
    #pragma unroll
    for (int k = 0; k < WREG; ++k) wreg[k] = mat[grow * HH + k];
    float* wsm = wsAll + jid * WSMK * HH;
    for (int kk = 0; kk < WSMK; ++kk) wsm[kk * HH + r] = mat[grow * HH + WREG + kk];

    if (tid < HH) {
        int gr = (tid >> 5) * HH + cu0 + (tid & 31);
        b1sm[tid] = bi1[gr] + bh1[gr];
    }
    for (int i = tid; i < 2 * HH * BG; i += 384) { h0buf[i] = 0.0f; h2buf[i] = 0.0f; }
    __syncthreads();
    CLUSTER_ARRIVE();   // zeros + smem weights visible cluster-wide before step 0
    CLUSTER_WAIT();

    const uint32_t h0base = (uint32_t)__cvta_generic_to_shared(h0buf);
    const uint32_t h2base = (uint32_t)__cvta_generic_to_shared(h2buf);

    // state-update identity (threads 0..255): unit su, batch sb
    const int su = (tid & 127) >> 2;
    const int sb = tid & 3;
    float c0 = 0.0f, c1 = 0.0f;
    const int durb = dur[bg0 + sb];

    float4 p = make_float4(0.f, 0.f, 0.f, 0.f);
    if (jid == 0) p = __ldcs((const float4*)&g_pre[br][0][grow][bg0]);

    for (int s = 0; s <= TT; ++s) {
        const float* h0prev = h0buf + ((s + 1) & 1) * (HH * BG);
        const float* h2prev = h2buf + ((s + 1) & 1) * (HH * BG);

        // ---- gate partial loops ----
        const bool active = (jid == 0) ? (s < TT) : (s >= 1);
        if (active) {
            unsigned long long a01, a23;
            if (jid == 0) {
                a01 = pack2(p.x, p.y); a23 = pack2(p.z, p.w);
            } else if (jid == 1) {
                float bb = b1sm[r];
                a01 = pack2(bb, bb); a23 = a01;
            } else {
                a01 = 0ull; a23 = 0ull;
            }
            const float* hsrc = (jid == 2) ? h2prev : h0prev;
            #pragma unroll
            for (int k = 0; k < WREG; ++k) {
                ulonglong2 v = *(const ulonglong2*)&hsrc[k * BG];
                unsigned long long wp = pack2(wreg[k], wreg[k]);
                fma2(a01, wp, v.x);
                fma2(a23, wp, v.y);
            }
            #pragma unroll 8
            for (int kk = 0; kk < WSMK; ++kk) {
                float w = wsm[kk * HH + r];
                unsigned long long wp = pack2(w, w);
                ulonglong2 v = *(const ulonglong2*)&hsrc[(WREG + kk) * BG];
                fma2(a01, wp, v.x);
                fma2(a23, wp, v.y);
            }
            ((ulonglong2*)gall)[jid * HH + r] = make_ulonglong2(a01, a23);
        }

        // ---- per-job-group sync (decouple L0 from L1 tail) ----
        if (jid == 0) BAR_SYNC(1, 128);
        else          BAR_SYNC(2, 256);

        // ---- state updates + DSMEM broadcast ----
        if (tid < 128) {
            if (s < TT) {
                const float* g0 = gall;
                float ip = g0[(0  + su) * BG + sb];
                float fp = g0[(32 + su) * BG + sb];
                float gp = g0[(64 + su) * BG + sb];
                float op = g0[(96 + su) * BG + sb];
                c0 = sigf(fp) * c0 + sigf(ip) * tanhfast(gp);
                float h = sigf(op) * tanhfast(c0);
                uint32_t la = h0base + (uint32_t)((((s & 1) * HH + cu0 + su) * BG + sb) * 4);
                #pragma unroll
                for (uint32_t rr = 0; rr < CSZ; ++rr) st_cluster_f32(la, rr, h);
            }
        } else if (tid < 256) {
            if (s >= 1) {
                const float* ga = gall + 1 * HH * BG;
                const float* gb = gall + 2 * HH * BG;
                float ip = ga[(0  + su) * BG + sb] + gb[(0  + su) * BG + sb];
                float fp = ga[(32 + su) * BG + sb] + gb[(32 + su) * BG + sb];
                float gp = ga[(64 + su) * BG + sb] + gb[(64 + su) * BG + sb];
                float op = ga[(96 + su) * BG + sb] + gb[(96 + su) * BG + sb];
                c1 = sigf(fp) * c1 + sigf(ip) * tanhfast(gp);
                float h = sigf(op) * tanhfast(c1);
                uint32_t la = h2base + (uint32_t)((((s & 1) * HH + cu0 + su) * BG + sb) * 4);
                #pragma unroll
                for (uint32_t rr = 0; rr < CSZ; ++rr) st_cluster_f32(la, rr, h);
                if (s == durb) g_hf[br][cu0 + su][bg0 + sb] = h;
            }
        }

        // ---- split cluster barrier: arrive, prefetch in the gap, wait ----
        CLUSTER_ARRIVE();
        if (jid == 0 && s + 1 < TT)
            p = __ldcs((const float4*)&g_pre[br][s + 1][grow][bg0]);
        CLUSTER_WAIT();
    }
}

// ==================================================================
// Kernel 3: epilogue
// ==================================================================
__global__ void __launch_bounds__(64)
epilogue_kernel(const int* __restrict__ yv,
                const float* __restrict__ wcl, const float* __restrict__ bcl,
                const float* __restrict__ wcr, const float* __restrict__ bcr,
                const float* __restrict__ Wout, const float* __restrict__ bout,
                float* __restrict__ out)
{
    __shared__ float lsum[64];
    const int b = threadIdx.x;

    float hl[HH + 2], hr[HH + 2], y3[HH];
    hl[0] = 0.0f; hl[HH + 1] = 0.0f;
    hr[0] = 0.0f; hr[HH + 1] = 0.0f;
    for (int j = 0; j < HH; ++j) {
        hl[j + 1] = g_hf[0][j][b];
        hr[j + 1] = g_hf[1][j][b];
    }
    float wl0 = wcl[0], wl1 = wcl[1], wl2 = wcl[2], bl = bcl[0];
    float wr0 = wcr[0], wr1 = wcr[1], wr2 = wcr[2], br_ = bcr[0];
    for (int j = 0; j < HH; ++j) {
        float vl = wl0 * hl[j] + wl1 * hl[j + 1] + wl2 * hl[j + 2] + bl;
        float vr = wr0 * hr[j] + wr1 * hr[j + 1] + wr2 * hr[j + 2] + br_;
        y3[j] = vl + vr;
        out[ACT_OFF + b * HH + j] = tanhf(y3[j]) * 0.1f;
    }
    float logits[LL];
    float mx = -1e30f;
    for (int l = 0; l < LL; ++l) {
        float s = bout[l];
        for (int j = 0; j < HH; ++j) s += y3[j] * Wout[l * HH + j];
        logits[l] = s;
        mx = fmaxf(mx, s);
    }
    float den = 0.0f;
    for (int l = 0; l < LL; ++l) { logits[l] = expf(logits[l] - mx); den += logits[l]; }
    float inv = 1.0f / den;
    int yb = yv[b];
    float py = 0.0f, myloss = 0.0f;
    for (int l = 0; l < LL; ++l) {
        float pql = logits[l] * inv;
        logits[l] = pql;
        out[PRED_OFF + b * LL + l] = pql;
        if (l == yb) py = pql;
    }
    for (int l = 0; l < LL; ++l) {
        float pql = logits[l];
        float lp = fmaxf(logf(pql), -100.0f);
        float lq = fmaxf(logf(1.0f - pql), -100.0f);
        myloss += (l == yb) ? lp : lq;
    }
    int rank = 0;
    for (int l = 0; l < LL; ++l) {
        if (logits[l] > py) rank++;
        else if (logits[l] == py && l < yb) rank++;
    }
    out[ACC1_OFF + b] = (rank == 0) ? 1.0f : 0.0f;
    out[ACC3_OFF + b] = (rank < 3) ? 1.0f : 0.0f;

    lsum[b] = myloss;
    __syncthreads();
    if (b == 0) {
        float s = 0.0f;
        for (int i = 0; i < BATCH; ++i) s += lsum[i];
        out[0] = -s / (float)(BATCH * LL);
    }
}

// ==================================================================
extern "C" void kernel_launch(void* const* d_in, const int* in_sizes, int n_in,
                              void* d_out, int out_size) {
    (void)in_sizes; (void)n_in; (void)out_size;
    cudaFuncSetAttribute(pre_gemm_kernel, cudaFuncAttributeMaxDynamicSharedMemorySize,
                         GEMM_SMEM_FLOATS * (int)sizeof(float));
    cudaFuncSetAttribute(lstm_recurrent_kernel, cudaFuncAttributeMaxDynamicSharedMemorySize,
                         REC_SMEM_FLOATS * (int)sizeof(float));

    const float* xl  = (const float*)d_in[0];
    const float* xr  = (const float*)d_in[1];
    const float* xo  = (const float*)d_in[2];
    const int*   yv  = (const int*)d_in[3];
    const int*   isl = (const int*)d_in[4];
    const int*   isr = (const int*)d_in[5];
    const int*   dur = (const int*)d_in[6];

    pre_gemm_kernel<<<dim3(8, TT, 2), 128, GEMM_SMEM_FLOATS * sizeof(float)>>>(
        xl, xr, xo, isl, isr,
        (const float*)d_in[7],  (const float*)d_in[9],  (const float*)d_in[10],
        (const float*)d_in[15], (const float*)d_in[17], (const float*)d_in[18]);

    lstm_recurrent_kernel<<<128, 384, REC_SMEM_FLOATS * sizeof(float)>>>(
        (const float*)d_in[8],  (const float*)d_in[16],
        (const float*)d_in[11], (const float*)d_in[12],
        (const float*)d_in[13], (const float*)d_in[14],
        (const float*)d_in[19], (const float*)d_in[20],
        (const float*)d_in[21], (const float*)d_in[22],
        dur);

    epilogue_kernel<<<1, 64>>>(
        yv,
        (const float*)d_in[23], (const float*)d_in[24],
        (const float*)d_in[25], (const float*)d_in[26],
        (const float*)d_in[27], (const float*)d_in[28],
        (float*)d_out);
}

// round 12
// speedup vs baseline: 7.8233x; 1.0610x over previous
#include <cuda_runtime.h>
#include <math.h>
#include <stdint.h>

#define BATCH 64
#define TT    2048
#define HH    128
#define DIN   108
#define LL    37

#define BG    4      // batches per cluster
#define CSZ   4      // CTAs per cluster
#define UPC   32     // hidden units per CTA

#define WREG  112    // k-range held in registers
#define WSMK  16     // k-range held in smem

#define ACC1_OFF 1
#define ACC3_OFF 65
#define ACT_OFF  129
#define PRED_OFF (129 + BATCH*HH)

// ---------------- device scratch (static; no runtime allocation) ----------------
__device__ __align__(16) float g_pre[2][TT][512][BATCH];   // x@Wih0^T + (bih0+bhh0)
__device__ __align__(16) float g_hf[2][HH][BATCH];

__device__ __forceinline__ float sigf(float x)    { return 1.0f / (1.0f + __expf(-x)); }
__device__ __forceinline__ float tanhfast(float x){ return 2.0f / (1.0f + __expf(-2.0f * x)) - 1.0f; }

__device__ __forceinline__ unsigned long long pack2(float x, float y) {
    unsigned long long r;
    asm("mov.b64 %0, {%1, %2};" : "=l"(r) : "f"(x), "f"(y));
    return r;
}
__device__ __forceinline__ void fma2(unsigned long long& acc, unsigned long long w2,
                                     unsigned long long v2) {
    asm("fma.rn.f32x2 %0, %1, %2, %0;" : "+l"(acc) : "l"(w2), "l"(v2));
}
// async remote store, tx-tracked on the destination CTA's (phase-selected) mbarrier
__device__ __forceinline__ void st_async_f32(uint32_t saddr, uint32_t mbaddr,
                                             uint32_t rk, float v) {
    uint32_t ra, rb;
    asm volatile("mapa.shared::cluster.u32 %0, %1, %2;" : "=r"(ra) : "r"(saddr), "r"(rk));
    asm volatile("mapa.shared::cluster.u32 %0, %1, %2;" : "=r"(rb) : "r"(mbaddr), "r"(rk));
    asm volatile("st.async.shared::cluster.mbarrier::complete_tx::bytes.b32 [%0], %1, [%2];"
                 :: "r"(ra), "r"(__float_as_uint(v)), "r"(rb) : "memory");
}
__device__ __forceinline__ void mbar_expect_tx(uint32_t mbaddr, uint32_t tx) {
    asm volatile("mbarrier.arrive.expect_tx.shared.b64 _, [%0], %1;"
                 :: "r"(mbaddr), "r"(tx) : "memory");
}
__device__ __forceinline__ void mbar_wait_parity(uint32_t mbaddr, uint32_t parity) {
    uint32_t done;
    asm volatile(
        "{\n\t.reg .pred p;\n\t"
        "mbarrier.try_wait.parity.acquire.cluster.shared::cta.b64 p, [%1], %2;\n\t"
        "selp.b32 %0, 1, 0, p;\n\t}"
        : "=r"(done) : "r"(mbaddr), "r"(parity) : "memory");
    if (!done) {
        asm volatile(
            "{\n\t.reg .pred p;\n\t"
            "WL_%=:\n\t"
            "mbarrier.try_wait.parity.acquire.cluster.shared::cta.b64 p, [%0], %1, 0x989680;\n\t"
            "@p bra.uni WD_%=;\n\t"
            "bra.uni WL_%=;\n\t"
            "WD_%=:\n\t}"
            :: "r"(mbaddr), "r"(parity) : "memory");
    }
}
#define CLUSTER_SYNC() do { \
    asm volatile("barrier.cluster.arrive.aligned;" ::: "memory"); \
    asm volatile("barrier.cluster.wait.aligned;"   ::: "memory"); \
} while (0)
#define BAR_SYNC(id, cnt) asm volatile("bar.sync %0, %1;" :: "r"(id), "r"(cnt) : "memory")

// ==================================================================
// Kernel 1: precompute gate inputs  pre[br][t][row][b]
// ==================================================================
#define GX_XS 0
#define GX_WS (DIN*68)
#define GX_BS (GX_WS + 64*113)
#define GEMM_SMEM_FLOATS (GX_BS + 64)

__global__ void __launch_bounds__(128)
pre_gemm_kernel(const float* __restrict__ xl, const float* __restrict__ xr,
                const float* __restrict__ xo,
                const int* __restrict__ isl, const int* __restrict__ isr,
                const float* __restrict__ Wl, const float* __restrict__ bil, const float* __restrict__ bhl,
                const float* __restrict__ Wr, const float* __restrict__ bir, const float* __restrict__ bhr)
{
    extern __shared__ float sg[];
    float* xs  = sg + GX_XS;
    float* Wsm = sg + GX_WS;
    float* bsm = sg + GX_BS;

    const int rb  = blockIdx.x;
    const int t   = blockIdx.y;
    const int br  = blockIdx.z;
    const int tid = threadIdx.x;

    const float* xh  = br ? xr  : xl;
    const int*   ish = br ? isr : isl;
    const float* W   = br ? Wr  : Wl;
    const float* bi  = br ? bir : bil;
    const float* bh  = br ? bhr : bhl;

    for (int i = tid; i < BATCH * DIN; i += 128) {
        int b = i / DIN, k = i - b * DIN;
        float v;
        if (k < 99) v = xh[(b * TT + t) * 99 + k] * ((ish[b] != 0) ? 1.0f : 0.0f);
        else        v = xo[(b * TT + t) * 9 + (k - 99)];
        xs[k * 68 + b] = v;
    }
    for (int i = tid; i < 64 * DIN; i += 128) {
        int lr = i / DIN, k = i - lr * DIN;
        Wsm[lr * 113 + k] = W[(rb * 64 + lr) * DIN + k];
    }
    if (tid < 64) bsm[tid] = bi[rb * 64 + tid] + bh[rb * 64 + tid];
    __syncthreads();

    const int rg = tid >> 4;
    const int b4 = (tid & 15) * 4;

    float4 acc[8];
    #pragma unroll
    for (int j = 0; j < 8; ++j) {
        float bb = bsm[rg * 8 + j];
        acc[j] = make_float4(bb, bb, bb, bb);
    }
    #pragma unroll 4
    for (int k = 0; k < DIN; ++k) {
        float4 xv = *(const float4*)&xs[k * 68 + b4];
        #pragma unroll
        for (int j = 0; j < 8; ++j) {
            float w = Wsm[(rg * 8 + j) * 113 + k];
            acc[j].x += w * xv.x; acc[j].y += w * xv.y;
            acc[j].z += w * xv.z; acc[j].w += w * xv.w;
        }
    }
    #pragma unroll
    for (int j = 0; j < 8; ++j) {
        int row = rb * 64 + rg * 8 + j;
        *(float4*)&g_pre[br][t][row][b4] = acc[j];
    }
}

// ==================================================================
// Kernel 2: cluster-parallel wavefront recurrence, balanced 3-job split.
// Sync: st.async tx-tracked DOUBLE-BUFFERED mbarriers (phase s -> mbar[s&1]).
// Soundness: a peer emits phase s+1 (-> mbar[(s-1)&1]) only after receiving my
// phase-s stores, which I emit only after mbar[(s-1)&1] completed phase s-1 —
// so tx can never land on a still-pending older phase. Wait parity = (p>>1)&1.
// Exit: drain final phase, inval barriers, trailing CLUSTER_SYNC.
// ==================================================================
#define WS_OFF  0                        // ws[3][WSMK][128]
#define B1_OFF  (WS_OFF + 3*WSMK*HH)     // 128
#define H0_OFF  (B1_OFF + HH)            // 2 slots x 128 units x 4
#define H2_OFF  (H0_OFF + 2*HH*BG)
#define G_OFF   (H2_OFF + 2*HH*BG)       // g[3][128][4]
#define MB_OFF  (G_OFF + 3*HH*BG)        // 2 x u64 mbarrier (4 floats)
#define REC_SMEM_FLOATS (MB_OFF + 4)

__global__ void __launch_bounds__(384, 1) __cluster_dims__(CSZ, 1, 1)
lstm_recurrent_kernel(const float* __restrict__ Whh0_l, const float* __restrict__ Whh0_r,
                      const float* __restrict__ Wih1_l, const float* __restrict__ Whh1_l,
                      const float* __restrict__ bih1_l, const float* __restrict__ bhh1_l,
                      const float* __restrict__ Wih1_r, const float* __restrict__ Whh1_r,
                      const float* __restrict__ bih1_r, const float* __restrict__ bhh1_r,
                      const int* __restrict__ dur)
{
    extern __shared__ float sm[];
    float* wsAll = sm + WS_OFF;
    float* b1sm  = sm + B1_OFF;
    float* h0buf = sm + H0_OFF;    // [slot][unit(128)][b(4)]
    float* h2buf = sm + H2_OFF;
    float* gall  = sm + G_OFF;     // [jid][row(128)][b(4)]

    const int tid = threadIdx.x;
    const int blk = blockIdx.x;
    const int cid = blk >> 2;            // cluster id 0..31
    const int br  = cid >> 4;            // branch
    const int bg0 = (cid & 15) * BG;     // first batch of group

    uint32_t rank;
    asm("mov.u32 %0, %%cluster_ctarank;" : "=r"(rank));
    const int cu0 = (int)rank * UPC;

    const float* Whh0 = br ? Whh0_r : Whh0_l;
    const float* Wih1 = br ? Wih1_r : Wih1_l;
    const float* Whh1 = br ? Whh1_r : Whh1_l;
    const float* bi1  = br ? bih1_r : bih1_l;
    const float* bh1  = br ? bhh1_r : bhh1_l;

    const int jid = tid >> 7;            // 0=L0, 1=L1a(Wih1), 2=L1b(Whh1)
    const int r   = tid & 127;           // gate-row
    const int grow = (r >> 5) * HH + cu0 + (r & 31);

    const float* mat = (jid == 0) ? Whh0 : ((jid == 1) ? Wih1 : Whh1);

    // ---- weights: k [0,WREG) -> registers; k [WREG,128) -> smem [kk][r] ----
    float wreg[WREG];
    #pragma unroll
    for (int k = 0; k < WREG; ++k) wreg[k] = mat[grow * HH + k];
    float* wsm = wsAll + jid * WSMK * HH;
    for (int kk = 0; kk < WSMK; ++kk) wsm[kk * HH + r] = mat[grow * HH + WREG + kk];

    if (tid < HH) {
        int gr = (tid >> 5) * HH + cu0 + (tid & 31);
        b1sm[tid] = bi1[gr] + bh1[gr];
    }
    for (int i = tid; i < 2 * HH * BG; i += 384) { h0buf[i] = 0.0f; h2buf[i] = 0.0f; }

    const uint32_t mbar0 = (uint32_t)__cvta_generic_to_shared(sm + MB_OFF);
    const uint32_t mbar1 = mbar0 + 8u;
    if (tid == 0) {
        asm volatile("mbarrier.init.shared.b64 [%0], %1;" :: "r"(mbar0), "r"(1) : "memory");
        asm volatile("mbarrier.init.shared.b64 [%0], %1;" :: "r"(mbar1), "r"(1) : "memory");
        mbar_expect_tx(mbar0, 2048u);   // phase 0: h0 only
        mbar_expect_tx(mbar1, 4096u);   // phase 1: h0 + h2
    }
    __syncthreads();
    CLUSTER_SYNC();   // barriers armed + zeros + smem weights visible before step 0

    const uint32_t h0base = (uint32_t)__cvta_generic_to_shared(h0buf);
    const uint32_t h2base = (uint32_t)__cvta_generic_to_shared(h2buf);

    const int su = (tid & 127) >> 2;     // unit
    const int sb = tid & 3;              // batch
    float c0 = 0.0f, c1 = 0.0f;
    const int durb = dur[bg0 + sb];

    float4 p = make_float4(0.f, 0.f, 0.f, 0.f);
    if (jid == 0) p = __ldcs((const float4*)&g_pre[br][0][grow][bg0]);

    for (int s = 0; s <= TT; ++s) {
        if (s > 0) {
            const uint32_t mbprev = ((s - 1) & 1) ? mbar1 : mbar0;
            mbar_wait_parity(mbprev, (unsigned)(((s - 1) >> 1) & 1));   // phase s-1 delivered
            if (tid == 0 && s + 1 <= TT) {  // re-arm this barrier for phase s+1
                uint32_t tx = ((s + 1 < TT) ? 2048u : 0u) + 2048u;      // s+1 >= 1 always
                mbar_expect_tx(mbprev, tx);
            }
        }
        const uint32_t mbcur = (s & 1) ? mbar1 : mbar0;

        const float* h0prev = h0buf + ((s + 1) & 1) * (HH * BG);
        const float* h2prev = h2buf + ((s + 1) & 1) * (HH * BG);

        // ---- gate partial loops ----
        const bool active = (jid == 0) ? (s < TT) : (s >= 1);
        if (active) {
            unsigned long long a01, a23;
            if (jid == 0) {
                a01 = pack2(p.x, p.y); a23 = pack2(p.z, p.w);
            } else if (jid == 1) {
                float bb = b1sm[r];
                a01 = pack2(bb, bb); a23 = a01;
            } else {
                a01 = 0ull; a23 = 0ull;
            }
            const float* hsrc = (jid == 2) ? h2prev : h0prev;
            #pragma unroll
            for (int k = 0; k < WREG; ++k) {
                ulonglong2 v = *(const ulonglong2*)&hsrc[k * BG];
                unsigned long long wp = pack2(wreg[k], wreg[k]);
                fma2(a01, wp, v.x);
                fma2(a23, wp, v.y);
            }
            #pragma unroll 8
            for (int kk = 0; kk < WSMK; ++kk) {
                float w = wsm[kk * HH + r];
                unsigned long long wp = pack2(w, w);
                ulonglong2 v = *(const ulonglong2*)&hsrc[(WREG + kk) * BG];
                fma2(a01, wp, v.x);
                fma2(a23, wp, v.y);
            }
            ((ulonglong2*)gall)[jid * HH + r] = make_ulonglong2(a01, a23);
        }

        // ---- per-job-group sync (decouple L0 from L1 tail) ----
        if (jid == 0) BAR_SYNC(1, 128);
        else          BAR_SYNC(2, 256);

        // ---- state updates + tx-tracked DSMEM broadcast (phase s -> mbar[s&1]) ----
        if (tid < 128) {
            if (s < TT) {
                const float* g0 = gall;
                float ip = g0[(0  + su) * BG + sb];
                float fp = g0[(32 + su) * BG + sb];
                float gp = g0[(64 + su) * BG + sb];
                float op = g0[(96 + su) * BG + sb];
                c0 = sigf(fp) * c0 + sigf(ip) * tanhfast(gp);
                float h = sigf(op) * tanhfast(c0);
                uint32_t la = h0base + (uint32_t)((((s & 1) * HH + cu0 + su) * BG + sb) * 4);
                #pragma unroll
                for (uint32_t rr = 0; rr < CSZ; ++rr) st_async_f32(la, mbcur, rr, h);
            }
        } else if (tid < 256) {
            if (s >= 1) {
                const float* ga = gall + 1 * HH * BG;
                const float* gb = gall + 2 * HH * BG;
                float ip = ga[(0  + su) * BG + sb] + gb[(0  + su) * BG + sb];
                float fp = ga[(32 + su) * BG + sb] + gb[(32 + su) * BG + sb];
                float gp = ga[(64 + su) * BG + sb] + gb[(64 + su) * BG + sb];
                float op = ga[(96 + su) * BG + sb] + gb[(96 + su) * BG + sb];
                c1 = sigf(fp) * c1 + sigf(ip) * tanhfast(gp);
                float h = sigf(op) * tanhfast(c1);
                uint32_t la = h2base + (uint32_t)((((s & 1) * HH + cu0 + su) * BG + sb) * 4);
                #pragma unroll
                for (uint32_t rr = 0; rr < CSZ; ++rr) st_async_f32(la, mbcur, rr, h);
                if (s == durb) g_hf[br][cu0 + su][bg0 + sb] = h;
            }
        }

        // prefetch next step's pre-GEMM inputs (hidden behind next wait)
        if (jid == 0 && s + 1 < TT)
            p = __ldcs((const float4*)&g_pre[br][s + 1][grow][bg0]);
    }

    // drain final phase, invalidate barriers, full cluster quiesce before exit
    mbar_wait_parity((TT & 1) ? mbar1 : mbar0, (unsigned)((TT >> 1) & 1));
    __syncthreads();
    if (tid == 0) {
        asm volatile("mbarrier.inval.shared.b64 [%0];" :: "r"(mbar0) : "memory");
        asm volatile("mbarrier.inval.shared.b64 [%0];" :: "r"(mbar1) : "memory");
    }
    CLUSTER_SYNC();
}

// ==================================================================
// Kernel 3: epilogue
// ==================================================================
__global__ void __launch_bounds__(64)
epilogue_kernel(const int* __restrict__ yv,
                const float* __restrict__ wcl, const float* __restrict__ bcl,
                const float* __restrict__ wcr, const float* __restrict__ bcr,
                const float* __restrict__ Wout, const float* __restrict__ bout,
                float* __restrict__ out)
{
    __shared__ float lsum[64];
    const int b = threadIdx.x;

    float hl[HH + 2], hr[HH + 2], y3[HH];
    hl[0] = 0.0f; hl[HH + 1] = 0.0f;
    hr[0] = 0.0f; hr[HH + 1] = 0.0f;
    for (int j = 0; j < HH; ++j) {
        hl[j + 1] = g_hf[0][j][b];
        hr[j + 1] = g_hf[1][j][b];
    }
    float wl0 = wcl[0], wl1 = wcl[1], wl2 = wcl[2], bl = bcl[0];
    float wr0 = wcr[0], wr1 = wcr[1], wr2 = wcr[2], br_ = bcr[0];
    for (int j = 0; j < HH; ++j) {
        float vl = wl0 * hl[j] + wl1 * hl[j + 1] + wl2 * hl[j + 2] + bl;
        float vr = wr0 * hr[j] + wr1 * hr[j + 1] + wr2 * hr[j + 2] + br_;
        y3[j] = vl + vr;
        out[ACT_OFF + b * HH + j] = tanhf(y3[j]) * 0.1f;
    }
    float logits[LL];
    float mx = -1e30f;
    for (int l = 0; l < LL; ++l) {
        float s = bout[l];
        for (int j = 0; j < HH; ++j) s += y3[j] * Wout[l * HH + j];
        logits[l] = s;
        mx = fmaxf(mx, s);
    }
    float den = 0.0f;
    for (int l = 0; l < LL; ++l) { logits[l] = expf(logits[l] - mx); den += logits[l]; }
    float inv = 1.0f / den;
    int yb = yv[b];
    float py = 0.0f, myloss = 0.0f;
    for (int l = 0; l < LL; ++l) {
        float pql = logits[l] * inv;
        logits[l] = pql;
        out[PRED_OFF + b * LL + l] = pql;
        if (l == yb) py = pql;
    }
    for (int l = 0; l < LL; ++l) {
        float pql = logits[l];
        float lp = fmaxf(logf(pql), -100.0f);
        float lq = fmaxf(logf(1.0f - pql), -100.0f);
        myloss += (l == yb) ? lp : lq;
    }
    int rank = 0;
    for (int l = 0; l < LL; ++l) {
        if (logits[l] > py) rank++;
        else if (logits[l] == py && l < yb) rank++;
    }
    out[ACC1_OFF + b] = (rank == 0) ? 1.0f : 0.0f;
    out[ACC3_OFF + b] = (rank < 3) ? 1.0f : 0.0f;

    lsum[b] = myloss;
    __syncthreads();
    if (b == 0) {
        float s = 0.0f;
        for (int i = 0; i < BATCH; ++i) s += lsum[i];
        out[0] = -s / (float)(BATCH * LL);
    }
}

// ==================================================================
extern "C" void kernel_launch(void* const* d_in, const int* in_sizes, int n_in,
                              void* d_out, int out_size) {
    (void)in_sizes; (void)n_in; (void)out_size;
    cudaFuncSetAttribute(pre_gemm_kernel, cudaFuncAttributeMaxDynamicSharedMemorySize,
                         GEMM_SMEM_FLOATS * (int)sizeof(float));
    cudaFuncSetAttribute(lstm_recurrent_kernel, cudaFuncAttributeMaxDynamicSharedMemorySize,
                         REC_SMEM_FLOATS * (int)sizeof(float));

    const float* xl  = (const float*)d_in[0];
    const float* xr  = (const float*)d_in[1];
    const float* xo  = (const float*)d_in[2];
    const int*   yv  = (const int*)d_in[3];
    const int*   isl = (const int*)d_in[4];
    const int*   isr = (const int*)d_in[5];
    const int*   dur = (const int*)d_in[6];

    pre_gemm_kernel<<<dim3(8, TT, 2), 128, GEMM_SMEM_FLOATS * sizeof(float)>>>(
        xl, xr, xo, isl, isr,
        (const float*)d_in[7],  (const float*)d_in[9],  (const float*)d_in[10],
        (const float*)d_in[15], (const float*)d_in[17], (const float*)d_in[18]);

    lstm_recurrent_kernel<<<128, 384, REC_SMEM_FLOATS * sizeof(float)>>>(
        (const float*)d_in[8],  (const float*)d_in[16],
        (const float*)d_in[11], (const float*)d_in[12],
        (const float*)d_in[13], (const float*)d_in[14],
        (const float*)d_in[19], (const float*)d_in[20],
        (const float*)d_in[21], (const float*)d_in[22],
        dur);

    epilogue_kernel<<<1, 64>>>(
        yv,
        (const float*)d_in[23], (const float*)d_in[24],
        (const float*)d_in[25], (const float*)d_in[26],
        (const float*)d_in[27], (const float*)d_in[28],
        (float*)d_out);
}